// round 11
// baseline (speedup 1.0000x reference)
#include <cuda_runtime.h>
#include <cuda_fp16.h>
#include <math.h>
#include <float.h>
#include <stdint.h>

// Problem constants
#define PB 2
#define PS 4096
#define PD 2048
#define PD3 6144              // fused QKV output width
#define PH 16
#define PHD 128
#define PW 128
#define PNC 32
#define PT (PB*PS)            // 8192 tokens

// Scratch (allocation-free)
__device__ __half g_qkv[PT * PD3];              // fused fp16 Q|K|V
__device__ __half g_xh [PT * PD];               // fp16 x
__device__ __half g_wh [4 * (size_t)PD * PD];   // fp16 wq,wk,wv,wo (concat)
__device__ __half g_aoh[PT * PD];               // fp16 attention output
__device__ float  g_cos[PW * 64];               // rope tables
__device__ float  g_sin[PW * 64];

// ---------------------------------------------------------------------------
// PTX helpers
// ---------------------------------------------------------------------------
__device__ __forceinline__ void cp_async16(uint32_t saddr, const void* gptr) {
    asm volatile("cp.async.cg.shared.global [%0], [%1], 16;\n" :: "r"(saddr), "l"(gptr));
}
__device__ __forceinline__ void mma_f16(float* c, const uint32_t* a, const uint32_t* b) {
    asm volatile(
        "mma.sync.aligned.m16n8k16.row.col.f32.f16.f16.f32 "
        "{%0,%1,%2,%3}, {%4,%5,%6,%7}, {%8,%9}, {%0,%1,%2,%3};"
        : "+f"(c[0]), "+f"(c[1]), "+f"(c[2]), "+f"(c[3])
        : "r"(a[0]), "r"(a[1]), "r"(a[2]), "r"(a[3]), "r"(b[0]), "r"(b[1]));
}
__device__ __forceinline__ void ldsm_x4(uint32_t* r, uint32_t addr) {
    asm volatile("ldmatrix.sync.aligned.m8n8.x4.shared.b16 {%0,%1,%2,%3}, [%4];"
        : "=r"(r[0]), "=r"(r[1]), "=r"(r[2]), "=r"(r[3]) : "r"(addr));
}
__device__ __forceinline__ void ldsm_x4_t(uint32_t* r, uint32_t addr) {
    asm volatile("ldmatrix.sync.aligned.m8n8.x4.trans.shared.b16 {%0,%1,%2,%3}, [%4];"
        : "=r"(r[0]), "=r"(r[1]), "=r"(r[2]), "=r"(r[3]) : "r"(addr));
}

// ---------------------------------------------------------------------------
// fp16 tensor-core GEMM: C[m,n] = sum_k A[m,k] * W[n,k]   (fp32 accumulate)
// CTA 128x256, BK=64 halves, 8 warps (2m x 4n), warp tile 64x64.
// 3-stage circular cp.async pipeline, fragment double-buffering,
// ldmatrix fragments, m16n8k16 HMMA. 1 CTA/SM (high regs, smem 166KB).
// Warp tile 64x64 halves smem read traffic per FLOP vs 64x32.
// ---------------------------------------------------------------------------
#define BM 128
#define BN 256
#define BKH 64
#define KST 72                 // BKH + 8 pad (144B rows; ldmatrix conflict-free)
#define NST 3
#define ASTAGE (BM * KST)      // halves per A stage (9216)
#define BSTAGE (BN * KST)      // halves per B stage (18432)

template <typename OutT>
__global__ __launch_bounds__(256, 1)
void gemm_f16(const __half* __restrict__ A, const __half* __restrict__ W,
              OutT* __restrict__ C, int M, int N, int K)
{
    extern __shared__ __half smh[];
    __half* sA = smh;                        // [NST][128][72]
    __half* sB = smh + NST * ASTAGE;         // [NST][256][72]

    const int tid  = threadIdx.x;
    const int bm   = blockIdx.y * BM;
    const int bn   = blockIdx.x * BN;
    const int warp = tid >> 5;
    const int lane = tid & 31;
    const int wm   = (warp & 1) * 64;        // warp m offset (0/64)
    const int wn   = (warp >> 1) * 64;       // warp n offset (0/64/128/192)
    const int lr   = lane >> 2;
    const int lc   = lane & 3;

    float acc[4][8][4];
#pragma unroll
    for (int i = 0; i < 4; i++)
#pragma unroll
        for (int j = 0; j < 8; j++)
#pragma unroll
            for (int r = 0; r < 4; r++) acc[i][j][r] = 0.0f;

    const int T = K / BKH;                   // 32

    // loader: 3072 16B chunks per stage, 12 per thread
    auto load_tile = [&](int t, int buf) {
        const int k0 = t * BKH;
        __half* a_dst = sA + buf * ASTAGE;
        __half* b_dst = sB + buf * BSTAGE;
#pragma unroll
        for (int i = 0; i < 12; i++) {
            int c = tid + i * 256;           // 0..3071
            if (c < 1024) {
                int r  = c >> 3;
                int c8 = (c & 7) * 8;
                cp_async16((uint32_t)__cvta_generic_to_shared(a_dst + r * KST + c8),
                           &A[(size_t)(bm + r) * K + k0 + c8]);
            } else {
                int cb = c - 1024;
                int r  = cb >> 3;
                int c8 = (cb & 7) * 8;
                cp_async16((uint32_t)__cvta_generic_to_shared(b_dst + r * KST + c8),
                           &W[(size_t)(bn + r) * K + k0 + c8]);
            }
        }
        asm volatile("cp.async.commit_group;\n");
    };

    load_tile(0, 0);
    load_tile(1, 1);

    // ldmatrix lane address components (halves)
    const int a_r = (lane & 15);
    const int a_c = (lane >> 4) * 8;
    const int b_r = (lane & 7) + (lane >> 4) * 8;
    const int b_c = ((lane >> 3) & 1) * 8;

    int buf = 0;
    for (int t = 0; t < T; t++) {
        if (t < T - 1) { asm volatile("cp.async.wait_group 1;\n"); }
        else           { asm volatile("cp.async.wait_group 0;\n"); }
        __syncthreads();

        if (t + 2 < T) {
            int nb = buf + 2; if (nb >= NST) nb -= NST;
            load_tile(t + 2, nb);
        }

        const __half* a_s = sA + buf * ASTAGE;
        const __half* b_s = sB + buf * BSTAGE;

        // fragment double buffers
        uint32_t af[2][4][4];
        uint32_t bf[2][4][4];

        // prime kk=0
#pragma unroll
        for (int mt = 0; mt < 4; mt++)
            ldsm_x4(af[0][mt], (uint32_t)__cvta_generic_to_shared(
                        a_s + (wm + mt * 16 + a_r) * KST + a_c));
#pragma unroll
        for (int p = 0; p < 4; p++)
            ldsm_x4(bf[0][p], (uint32_t)__cvta_generic_to_shared(
                        b_s + (wn + p * 16 + b_r) * KST + b_c));

#pragma unroll
        for (int kk = 0; kk < 4; kk++) {
            const int cur = kk & 1;
            const int nxt = cur ^ 1;
            if (kk < 3) {
                const int kb = (kk + 1) * 16;
#pragma unroll
                for (int mt = 0; mt < 4; mt++)
                    ldsm_x4(af[nxt][mt], (uint32_t)__cvta_generic_to_shared(
                                a_s + (wm + mt * 16 + a_r) * KST + kb + a_c));
#pragma unroll
                for (int p = 0; p < 4; p++)
                    ldsm_x4(bf[nxt][p], (uint32_t)__cvta_generic_to_shared(
                                b_s + (wn + p * 16 + b_r) * KST + kb + b_c));
            }
#pragma unroll
            for (int mt = 0; mt < 4; mt++)
#pragma unroll
                for (int n8 = 0; n8 < 8; n8++)
                    mma_f16(acc[mt][n8], af[cur][mt], &bf[cur][n8 >> 1][(n8 & 1) * 2]);
        }
        buf++; if (buf == NST) buf = 0;
    }

#pragma unroll
    for (int mt = 0; mt < 4; mt++) {
#pragma unroll
        for (int n8 = 0; n8 < 8; n8++) {
            int r0 = bm + wm + mt * 16 + lr;
            int cc = bn + wn + n8 * 8 + 2 * lc;
            if (sizeof(OutT) == 4) {
                float* Cf = (float*)C;
                *(float2*)&Cf[(size_t)(r0    ) * N + cc] = make_float2(acc[mt][n8][0], acc[mt][n8][1]);
                *(float2*)&Cf[(size_t)(r0 + 8) * N + cc] = make_float2(acc[mt][n8][2], acc[mt][n8][3]);
            } else {
                __half* Ch = (__half*)C;
                __half2 h0 = __floats2half2_rn(acc[mt][n8][0], acc[mt][n8][1]);
                __half2 h1 = __floats2half2_rn(acc[mt][n8][2], acc[mt][n8][3]);
                *(uint32_t*)&Ch[(size_t)(r0    ) * N + cc] = *(uint32_t*)&h0;
                *(uint32_t*)&Ch[(size_t)(r0 + 8) * N + cc] = *(uint32_t*)&h1;
            }
        }
    }
}

// ---------------------------------------------------------------------------
// Fused prep: x -> fp16, and 4 weights -> concat fp16, one launch.
// ---------------------------------------------------------------------------
#define N4X (PT * PD / 4)          // 4,194,304
#define N4W (PD * PD / 4)          // 1,048,576

__global__ void prep_kernel(const float4* __restrict__ x,
                            const float4* __restrict__ w0, const float4* __restrict__ w1,
                            const float4* __restrict__ w2, const float4* __restrict__ w3,
                            __half* __restrict__ xh, __half* __restrict__ wh)
{
    int i = blockIdx.x * blockDim.x + threadIdx.x;
    float4 v;
    __half* dst;
    if (i < N4X) {
        v = x[i];
        dst = xh + (size_t)i * 4;
    } else {
        int j   = i - N4X;
        int sel = j >> 20;                    // j / N4W
        int rem = j & (N4W - 1);
        const float4* s = (sel == 0) ? w0 : (sel == 1) ? w1 : (sel == 2) ? w2 : w3;
        v = s[rem];
        dst = wh + (size_t)j * 4;
    }
    __half2 h0 = __floats2half2_rn(v.x, v.y);
    __half2 h1 = __floats2half2_rn(v.z, v.w);
    uint2 o;
    o.x = *(uint32_t*)&h0;
    o.y = *(uint32_t*)&h1;
    *(uint2*)dst = o;
}

// ---------------------------------------------------------------------------
// RoPE cos/sin tables
// ---------------------------------------------------------------------------
__global__ void rope_table_kernel(float* __restrict__ ct, float* __restrict__ st)
{
    int t = blockIdx.x * blockDim.x + threadIdx.x;
    if (t >= PW * 64) return;
    int w = t >> 6;
    int j = t & 63;
    const float c_ln = 9.210340371976184f / 64.0f;
    float freq = (float)w * expf(-(float)j * c_ln);
    ct[t] = cosf(freq);
    st[t] = sinf(freq);
}

// ---------------------------------------------------------------------------
// Tensor-core block-local attention with fused RoPE, fp16 QKV input.
// One CTA per (chunk, head, batch); 8 warps, warp w owns 16 query rows.
// ---------------------------------------------------------------------------
#define AST 136                 // smem row stride in halves (272B)

__global__ __launch_bounds__(256, 1)
void attn_mma(const __half* __restrict__ QKV, const float* __restrict__ mask,
              const float* __restrict__ ctab, const float* __restrict__ stab,
              __half* __restrict__ O)
{
    extern __shared__ __half sh[];
    __half* sQ = sh;                   // [128][136]
    __half* sK = sh + 128 * AST;
    __half* sV = sh + 2 * 128 * AST;

    const int c = blockIdx.x;
    const int h = blockIdx.y;
    const int b = blockIdx.z;
    const int tid  = threadIdx.x;
    const int warp = tid >> 5;
    const int lane = tid & 31;
    const int lr   = lane >> 2;
    const int lc   = lane & 3;
    const int m0   = warp * 16;

    const int tb    = b * PS + c * PW;
    const int cbase = h * PHD;

    // ---- Load Q,K with fused RoPE (fp16 source; pairs d and d+64) ----
#pragma unroll
    for (int l = 0; l < 8; l++) {
        int f  = tid + l * 256;            // 0..2047 = 128 rows x 16 chunks
        int r  = f >> 4;
        int d4 = (f & 15) << 2;            // 0..60
        size_t g0 = (size_t)(tb + r) * PD3 + cbase + d4;
        uint2 uqa = *(const uint2*)&QKV[g0];
        uint2 uqb = *(const uint2*)&QKV[g0 + 64];
        uint2 uka = *(const uint2*)&QKV[g0 + PD];
        uint2 ukb = *(const uint2*)&QKV[g0 + PD + 64];
        float2 qa01 = __half22float2(*(__half2*)&uqa.x);
        float2 qa23 = __half22float2(*(__half2*)&uqa.y);
        float2 qb01 = __half22float2(*(__half2*)&uqb.x);
        float2 qb23 = __half22float2(*(__half2*)&uqb.y);
        float2 ka01 = __half22float2(*(__half2*)&uka.x);
        float2 ka23 = __half22float2(*(__half2*)&uka.y);
        float2 kb01 = __half22float2(*(__half2*)&ukb.x);
        float2 kb23 = __half22float2(*(__half2*)&ukb.y);
        float4 cv = *(const float4*)&ctab[r * 64 + d4];
        float4 sv = *(const float4*)&stab[r * 64 + d4];

        __half2 h0, h1;
        uint2 u;
        h0 = __floats2half2_rn(qa01.x * cv.x - qb01.x * sv.x,
                               qa01.y * cv.y - qb01.y * sv.y);
        h1 = __floats2half2_rn(qa23.x * cv.z - qb23.x * sv.z,
                               qa23.y * cv.w - qb23.y * sv.w);
        u.x = *(uint32_t*)&h0; u.y = *(uint32_t*)&h1;
        *(uint2*)&sQ[r * AST + d4] = u;
        h0 = __floats2half2_rn(qb01.x * cv.x + qa01.x * sv.x,
                               qb01.y * cv.y + qa01.y * sv.y);
        h1 = __floats2half2_rn(qb23.x * cv.z + qa23.x * sv.z,
                               qb23.y * cv.w + qa23.y * sv.w);
        u.x = *(uint32_t*)&h0; u.y = *(uint32_t*)&h1;
        *(uint2*)&sQ[r * AST + d4 + 64] = u;
        h0 = __floats2half2_rn(ka01.x * cv.x - kb01.x * sv.x,
                               ka01.y * cv.y - kb01.y * sv.y);
        h1 = __floats2half2_rn(ka23.x * cv.z - kb23.x * sv.z,
                               ka23.y * cv.w - kb23.y * sv.w);
        u.x = *(uint32_t*)&h0; u.y = *(uint32_t*)&h1;
        *(uint2*)&sK[r * AST + d4] = u;
        h0 = __floats2half2_rn(kb01.x * cv.x + ka01.x * sv.x,
                               kb01.y * cv.y + ka01.y * sv.y);
        h1 = __floats2half2_rn(kb23.x * cv.z + ka23.x * sv.z,
                               kb23.y * cv.w + ka23.y * sv.w);
        u.x = *(uint32_t*)&h0; u.y = *(uint32_t*)&h1;
        *(uint2*)&sK[r * AST + d4 + 64] = u;
    }
    // ---- Load V (fp16, straight copy) ----
#pragma unroll
    for (int l = 0; l < 8; l++) {
        int f  = tid + l * 256;
        int r  = f >> 4;
        int d4 = (f & 15) << 3;            // 8-half chunks
        uint4 uv = *(const uint4*)&QKV[(size_t)(tb + r) * PD3 + cbase + 2 * PD + d4];
        *(uint4*)&sV[r * AST + d4] = uv;
    }
    __syncthreads();

    // ---- Phase 1: S = Q K^T ----
    float sacc[16][4];
#pragma unroll
    for (int i = 0; i < 16; i++)
#pragma unroll
        for (int j = 0; j < 4; j++) sacc[i][j] = 0.0f;

    const int a_r = m0 + (lane & 15);
    const int a_c = (lane >> 4) * 8;
    const int b_r = (lane & 7) + (lane >> 4) * 8;
    const int b_c = ((lane >> 3) & 1) * 8;

#pragma unroll
    for (int ks = 0; ks < 8; ks++) {
        const int kb = ks * 16;
        uint32_t af[4];
        ldsm_x4(af, (uint32_t)__cvta_generic_to_shared(sQ + a_r * AST + kb + a_c));
#pragma unroll
        for (int p = 0; p < 8; p++) {
            uint32_t bf[4];
            ldsm_x4(bf, (uint32_t)__cvta_generic_to_shared(
                        sK + (p * 16 + b_r) * AST + kb + b_c));
            mma_f16(sacc[2 * p    ], af, bf);
            mma_f16(sacc[2 * p + 1], af, bf + 2);
        }
    }

    const float scale = 0.08838834764831845f;
    const float NEG = -3.402823466e38f;
    const float* mrow0 = mask + (size_t)b * PS * PS
                       + (size_t)(c * PW + m0 + lr) * PS + c * PW;
    const float* mrow1 = mrow0 + 8 * PS;
#pragma unroll
    for (int nt = 0; nt < 16; nt++) {
        float2 mv0 = *(const float2*)&mrow0[nt * 8 + 2 * lc];
        float2 mv1 = *(const float2*)&mrow1[nt * 8 + 2 * lc];
        sacc[nt][0] = fmaxf(fmaf(sacc[nt][0], scale, mv0.x), NEG);
        sacc[nt][1] = fmaxf(fmaf(sacc[nt][1], scale, mv0.y), NEG);
        sacc[nt][2] = fmaxf(fmaf(sacc[nt][2], scale, mv1.x), NEG);
        sacc[nt][3] = fmaxf(fmaf(sacc[nt][3], scale, mv1.y), NEG);
    }

    // ---- softmax ----
    float mx0 = -FLT_MAX, mx1 = -FLT_MAX;
#pragma unroll
    for (int nt = 0; nt < 16; nt++) {
        mx0 = fmaxf(mx0, fmaxf(sacc[nt][0], sacc[nt][1]));
        mx1 = fmaxf(mx1, fmaxf(sacc[nt][2], sacc[nt][3]));
    }
    mx0 = fmaxf(mx0, __shfl_xor_sync(0xFFFFFFFF, mx0, 1));
    mx0 = fmaxf(mx0, __shfl_xor_sync(0xFFFFFFFF, mx0, 2));
    mx1 = fmaxf(mx1, __shfl_xor_sync(0xFFFFFFFF, mx1, 1));
    mx1 = fmaxf(mx1, __shfl_xor_sync(0xFFFFFFFF, mx1, 2));

    float sum0 = 0.f, sum1 = 0.f;
#pragma unroll
    for (int nt = 0; nt < 16; nt++) {
        sacc[nt][0] = __expf(sacc[nt][0] - mx0);
        sacc[nt][1] = __expf(sacc[nt][1] - mx0);
        sacc[nt][2] = __expf(sacc[nt][2] - mx1);
        sacc[nt][3] = __expf(sacc[nt][3] - mx1);
        sum0 += sacc[nt][0] + sacc[nt][1];
        sum1 += sacc[nt][2] + sacc[nt][3];
    }
    sum0 += __shfl_xor_sync(0xFFFFFFFF, sum0, 1);
    sum0 += __shfl_xor_sync(0xFFFFFFFF, sum0, 2);
    sum1 += __shfl_xor_sync(0xFFFFFFFF, sum1, 1);
    sum1 += __shfl_xor_sync(0xFFFFFFFF, sum1, 2);
    const float inv0 = 1.0f / sum0;
    const float inv1 = 1.0f / sum1;

    uint32_t pf[8][4];
#pragma unroll
    for (int ks = 0; ks < 8; ks++) {
        __half2 p0 = __floats2half2_rn(sacc[2 * ks][0] * inv0, sacc[2 * ks][1] * inv0);
        __half2 p1 = __floats2half2_rn(sacc[2 * ks][2] * inv1, sacc[2 * ks][3] * inv1);
        __half2 p2 = __floats2half2_rn(sacc[2 * ks + 1][0] * inv0, sacc[2 * ks + 1][1] * inv0);
        __half2 p3 = __floats2half2_rn(sacc[2 * ks + 1][2] * inv1, sacc[2 * ks + 1][3] * inv1);
        pf[ks][0] = *(uint32_t*)&p0;
        pf[ks][1] = *(uint32_t*)&p1;
        pf[ks][2] = *(uint32_t*)&p2;
        pf[ks][3] = *(uint32_t*)&p3;
    }

    // ---- Phase 2: O = P V ----
    float oacc[16][4];
#pragma unroll
    for (int i = 0; i < 16; i++)
#pragma unroll
        for (int j = 0; j < 4; j++) oacc[i][j] = 0.0f;

    const int v_r = (lane & 15);
    const int v_c = (lane >> 4) * 8;
#pragma unroll
    for (int ks = 0; ks < 8; ks++) {
        const int kb = ks * 16;
#pragma unroll
        for (int p = 0; p < 8; p++) {
            uint32_t bf[4];
            ldsm_x4_t(bf, (uint32_t)__cvta_generic_to_shared(
                          sV + (kb + v_r) * AST + p * 16 + v_c));
            mma_f16(oacc[2 * p    ], pf[ks], bf);
            mma_f16(oacc[2 * p + 1], pf[ks], bf + 2);
        }
    }

#pragma unroll
    for (int nt = 0; nt < 16; nt++) {
        int col = cbase + nt * 8 + 2 * lc;
        size_t g0 = (size_t)(tb + m0 + lr    ) * PD + col;
        size_t g1 = (size_t)(tb + m0 + lr + 8) * PD + col;
        __half2 o0 = __floats2half2_rn(oacc[nt][0], oacc[nt][1]);
        __half2 o1 = __floats2half2_rn(oacc[nt][2], oacc[nt][3]);
        *(uint32_t*)&O[g0] = *(uint32_t*)&o0;
        *(uint32_t*)&O[g1] = *(uint32_t*)&o1;
    }
}

// ---------------------------------------------------------------------------
extern "C" void kernel_launch(void* const* d_in, const int* in_sizes, int n_in,
                              void* d_out, int out_size)
{
    const float* x    = (const float*)d_in[0];
    const float* mask = (const float*)d_in[1];
    const float* wq   = (const float*)d_in[2];
    const float* wk   = (const float*)d_in[3];
    const float* wv   = (const float*)d_in[4];
    const float* wo   = (const float*)d_in[5];
    float* out = (float*)d_out;

    void *pqkv, *pxh, *pwh, *paoh, *pct, *pst;
    cudaGetSymbolAddress(&pqkv, g_qkv);
    cudaGetSymbolAddress(&pxh,  g_xh);
    cudaGetSymbolAddress(&pwh,  g_wh);
    cudaGetSymbolAddress(&paoh, g_aoh);
    cudaGetSymbolAddress(&pct,  g_cos);
    cudaGetSymbolAddress(&pst,  g_sin);
    __half* qkv  = (__half*)pqkv;
    __half* xh   = (__half*)pxh;
    __half* wh   = (__half*)pwh;
    __half* aoh  = (__half*)paoh;
    float*  ctab = (float*)pct;
    float*  stab = (float*)pst;

    // Fused prep + rope tables
    {
        int n4 = N4X + 4 * N4W;              // 8,388,608
        prep_kernel<<<n4 / 256, 256>>>((const float4*)x,
                                       (const float4*)wq, (const float4*)wk,
                                       (const float4*)wv, (const float4*)wo,
                                       xh, wh);
        rope_table_kernel<<<(PW * 64) / 256, 256>>>(ctab, stab);
    }

    size_t gsmem = (size_t)NST * (ASTAGE + BSTAGE) * sizeof(__half);   // 165,888 B
    cudaFuncSetAttribute(gemm_f16<__half>, cudaFuncAttributeMaxDynamicSharedMemorySize,
                         (int)gsmem);
    cudaFuncSetAttribute(gemm_f16<float>, cudaFuncAttributeMaxDynamicSharedMemorySize,
                         (int)gsmem);

    // Fused QKV projection: [8192 x 2048] x [6144 x 2048]^T -> fp16 [8192 x 6144]
    dim3 gqkv(PD3 / BN, PT / BM);            // 24 x 64
    gemm_f16<__half><<<gqkv, 256, gsmem>>>(xh, wh, qkv, PT, PD3, PD);

    // Attention (rope fused in loader)
    size_t asmem = (size_t)3 * 128 * AST * sizeof(__half);  // 104,448 B
    cudaFuncSetAttribute(attn_mma, cudaFuncAttributeMaxDynamicSharedMemorySize,
                         (int)asmem);
    attn_mma<<<dim3(PNC, PH, PB), 256, asmem>>>(qkv, mask, ctab, stab, aoh);

    // Output projection (fp32 out)
    dim3 gout(PD / BN, PT / BM);             // 8 x 64
    gemm_f16<float><<<gout, 256, gsmem>>>(aoh, wh + 3 * (size_t)PD * PD, out, PT, PD, PD);
}

// round 12
// speedup vs baseline: 1.0868x; 1.0868x over previous
#include <cuda_runtime.h>
#include <cuda_fp16.h>
#include <math.h>
#include <float.h>
#include <stdint.h>

// Problem constants
#define PB 2
#define PS 4096
#define PD 2048
#define PD3 6144              // fused QKV output width
#define PH 16
#define PHD 128
#define PW 128
#define PNC 32
#define PT (PB*PS)            // 8192 tokens

// Scratch (allocation-free)
__device__ __half g_qkv[PT * PD3];              // fused fp16 Q|K|V
__device__ __half g_xh [PT * PD];               // fp16 x
__device__ __half g_wh [4 * (size_t)PD * PD];   // fp16 wq,wk,wv,wo (concat)
__device__ __half g_aoh[PT * PD];               // fp16 attention output
__device__ float  g_cos[PW * 64];               // rope tables
__device__ float  g_sin[PW * 64];

// ---------------------------------------------------------------------------
// PTX helpers
// ---------------------------------------------------------------------------
__device__ __forceinline__ void cp_async16(uint32_t saddr, const void* gptr) {
    asm volatile("cp.async.cg.shared.global [%0], [%1], 16;\n" :: "r"(saddr), "l"(gptr));
}
__device__ __forceinline__ void mma_f16(float* c, const uint32_t* a, const uint32_t* b) {
    asm volatile(
        "mma.sync.aligned.m16n8k16.row.col.f32.f16.f16.f32 "
        "{%0,%1,%2,%3}, {%4,%5,%6,%7}, {%8,%9}, {%0,%1,%2,%3};"
        : "+f"(c[0]), "+f"(c[1]), "+f"(c[2]), "+f"(c[3])
        : "r"(a[0]), "r"(a[1]), "r"(a[2]), "r"(a[3]), "r"(b[0]), "r"(b[1]));
}
__device__ __forceinline__ void ldsm_x4(uint32_t* r, uint32_t addr) {
    asm volatile("ldmatrix.sync.aligned.m8n8.x4.shared.b16 {%0,%1,%2,%3}, [%4];"
        : "=r"(r[0]), "=r"(r[1]), "=r"(r[2]), "=r"(r[3]) : "r"(addr));
}
__device__ __forceinline__ void ldsm_x4_t(uint32_t* r, uint32_t addr) {
    asm volatile("ldmatrix.sync.aligned.m8n8.x4.trans.shared.b16 {%0,%1,%2,%3}, [%4];"
        : "=r"(r[0]), "=r"(r[1]), "=r"(r[2]), "=r"(r[3]) : "r"(addr));
}

// ---------------------------------------------------------------------------
// fp16 tensor-core GEMM: C[m,n] = sum_k A[m,k] * W[n,k]   (fp32 accumulate)
// CTA 128x128 with 128 threads = 4 warps (2m x 2n), warp tile 64x64.
// 2 CTAs/SM (independent barrier domains), 3-stage cp.async pipeline,
// double-buffered ldmatrix fragments, m16n8k16 HMMA.
// 64x64 warp tile: 8 LDSM per 32 HMMA (vs 6/16 at 64x32) -> fewer issue slots.
// ---------------------------------------------------------------------------
#define BM 128
#define BN 128
#define BKH 64
#define KST 72                 // BKH + 8 pad (144B rows; ldmatrix conflict-free)
#define NST 3
#define STG (BM * KST)         // halves per matrix stage (9216)

template <typename OutT>
__global__ __launch_bounds__(128, 2)
void gemm_f16(const __half* __restrict__ A, const __half* __restrict__ W,
              OutT* __restrict__ C, int M, int N, int K)
{
    extern __shared__ __half smh[];
    __half* sA = smh;                        // [NST][128][72]
    __half* sB = smh + NST * STG;            // [NST][128][72]

    const int tid  = threadIdx.x;
    const int bm   = blockIdx.y * BM;
    const int bn   = blockIdx.x * BN;
    const int warp = tid >> 5;
    const int lane = tid & 31;
    const int wm   = (warp & 1) * 64;        // warp m offset (0/64)
    const int wn   = (warp >> 1) * 64;       // warp n offset (0/64)
    const int lr   = lane >> 2;
    const int lc   = lane & 3;

    float acc[4][8][4];
#pragma unroll
    for (int i = 0; i < 4; i++)
#pragma unroll
        for (int j = 0; j < 8; j++)
#pragma unroll
            for (int r = 0; r < 4; r++) acc[i][j][r] = 0.0f;

    const int T = K / BKH;                   // 32

    // loader: 2048 16B chunks per stage, 16 per thread (128 threads)
    auto load_tile = [&](int t, int buf) {
        const int k0 = t * BKH;
        __half* a_dst = sA + buf * STG;
        __half* b_dst = sB + buf * STG;
#pragma unroll
        for (int i = 0; i < 16; i++) {
            int c   = tid + i * 128;         // 0..2047
            int isB = c >> 10;
            int idx = c & 1023;
            int r   = idx >> 3;
            int c8  = (idx & 7) * 8;
            const __half* g = isB ? &W[(size_t)(bn + r) * K + k0 + c8]
                                  : &A[(size_t)(bm + r) * K + k0 + c8];
            __half* d = (isB ? b_dst : a_dst) + r * KST + c8;
            cp_async16((uint32_t)__cvta_generic_to_shared(d), g);
        }
        asm volatile("cp.async.commit_group;\n");
    };

    load_tile(0, 0);
    load_tile(1, 1);

    // ldmatrix lane address components (halves)
    const int a_r = (lane & 15);
    const int a_c = (lane >> 4) * 8;
    const int b_r = (lane & 7) + (lane >> 4) * 8;
    const int b_c = ((lane >> 3) & 1) * 8;

    int buf = 0;
    for (int t = 0; t < T; t++) {
        if (t < T - 1) { asm volatile("cp.async.wait_group 1;\n"); }
        else           { asm volatile("cp.async.wait_group 0;\n"); }
        __syncthreads();

        if (t + 2 < T) {
            int nb = buf + 2; if (nb >= NST) nb -= NST;
            load_tile(t + 2, nb);
        }

        const __half* a_s = sA + buf * STG;
        const __half* b_s = sB + buf * STG;

        // fragment double buffers
        uint32_t af[2][4][4];
        uint32_t bf[2][4][4];

        // prime kk=0
#pragma unroll
        for (int mt = 0; mt < 4; mt++)
            ldsm_x4(af[0][mt], (uint32_t)__cvta_generic_to_shared(
                        a_s + (wm + mt * 16 + a_r) * KST + a_c));
#pragma unroll
        for (int p = 0; p < 4; p++)
            ldsm_x4(bf[0][p], (uint32_t)__cvta_generic_to_shared(
                        b_s + (wn + p * 16 + b_r) * KST + b_c));

#pragma unroll
        for (int kk = 0; kk < 4; kk++) {
            const int cur = kk & 1;
            const int nxt = cur ^ 1;
            if (kk < 3) {
                const int kb = (kk + 1) * 16;
#pragma unroll
                for (int mt = 0; mt < 4; mt++)
                    ldsm_x4(af[nxt][mt], (uint32_t)__cvta_generic_to_shared(
                                a_s + (wm + mt * 16 + a_r) * KST + kb + a_c));
#pragma unroll
                for (int p = 0; p < 4; p++)
                    ldsm_x4(bf[nxt][p], (uint32_t)__cvta_generic_to_shared(
                                b_s + (wn + p * 16 + b_r) * KST + kb + b_c));
            }
#pragma unroll
            for (int mt = 0; mt < 4; mt++)
#pragma unroll
                for (int n8 = 0; n8 < 8; n8++)
                    mma_f16(acc[mt][n8], af[cur][mt], &bf[cur][n8 >> 1][(n8 & 1) * 2]);
        }
        buf++; if (buf == NST) buf = 0;
    }

#pragma unroll
    for (int mt = 0; mt < 4; mt++) {
#pragma unroll
        for (int n8 = 0; n8 < 8; n8++) {
            int r0 = bm + wm + mt * 16 + lr;
            int cc = bn + wn + n8 * 8 + 2 * lc;
            if (sizeof(OutT) == 4) {
                float* Cf = (float*)C;
                *(float2*)&Cf[(size_t)(r0    ) * N + cc] = make_float2(acc[mt][n8][0], acc[mt][n8][1]);
                *(float2*)&Cf[(size_t)(r0 + 8) * N + cc] = make_float2(acc[mt][n8][2], acc[mt][n8][3]);
            } else {
                __half* Ch = (__half*)C;
                __half2 h0 = __floats2half2_rn(acc[mt][n8][0], acc[mt][n8][1]);
                __half2 h1 = __floats2half2_rn(acc[mt][n8][2], acc[mt][n8][3]);
                *(uint32_t*)&Ch[(size_t)(r0    ) * N + cc] = *(uint32_t*)&h0;
                *(uint32_t*)&Ch[(size_t)(r0 + 8) * N + cc] = *(uint32_t*)&h1;
            }
        }
    }
}

// ---------------------------------------------------------------------------
// Fused prep: x -> fp16, and 4 weights -> concat fp16, one launch.
// ---------------------------------------------------------------------------
#define N4X (PT * PD / 4)          // 4,194,304
#define N4W (PD * PD / 4)          // 1,048,576

__global__ void prep_kernel(const float4* __restrict__ x,
                            const float4* __restrict__ w0, const float4* __restrict__ w1,
                            const float4* __restrict__ w2, const float4* __restrict__ w3,
                            __half* __restrict__ xh, __half* __restrict__ wh)
{
    int i = blockIdx.x * blockDim.x + threadIdx.x;
    float4 v;
    __half* dst;
    if (i < N4X) {
        v = x[i];
        dst = xh + (size_t)i * 4;
    } else {
        int j   = i - N4X;
        int sel = j >> 20;                    // j / N4W
        int rem = j & (N4W - 1);
        const float4* s = (sel == 0) ? w0 : (sel == 1) ? w1 : (sel == 2) ? w2 : w3;
        v = s[rem];
        dst = wh + (size_t)j * 4;
    }
    __half2 h0 = __floats2half2_rn(v.x, v.y);
    __half2 h1 = __floats2half2_rn(v.z, v.w);
    uint2 o;
    o.x = *(uint32_t*)&h0;
    o.y = *(uint32_t*)&h1;
    *(uint2*)dst = o;
}

// ---------------------------------------------------------------------------
// RoPE cos/sin tables
// ---------------------------------------------------------------------------
__global__ void rope_table_kernel(float* __restrict__ ct, float* __restrict__ st)
{
    int t = blockIdx.x * blockDim.x + threadIdx.x;
    if (t >= PW * 64) return;
    int w = t >> 6;
    int j = t & 63;
    const float c_ln = 9.210340371976184f / 64.0f;
    float freq = (float)w * expf(-(float)j * c_ln);
    ct[t] = cosf(freq);
    st[t] = sinf(freq);
}

// ---------------------------------------------------------------------------
// Tensor-core block-local attention with fused RoPE, fp16 QKV input.
// One CTA per (chunk, head, batch, q-half): 128 threads = 4 warps, each warp
// owns 16 of the CTA's 64 query rows; K/V tiles full 128 rows. 2 CTAs/SM.
// ---------------------------------------------------------------------------
#define AST 136                 // smem row stride in halves (272B)

__global__ __launch_bounds__(128, 2)
void attn_mma(const __half* __restrict__ QKV, const float* __restrict__ mask,
              const float* __restrict__ ctab, const float* __restrict__ stab,
              __half* __restrict__ O)
{
    extern __shared__ __half sh[];
    __half* sQ = sh;                   // [64][136]
    __half* sK = sh + 64 * AST;        // [128][136]
    __half* sV = sh + (64 + 128) * AST; // [128][136]

    const int c  = blockIdx.x;
    const int h  = blockIdx.y;
    const int bz = blockIdx.z;
    const int b  = bz >> 1;
    const int qh = bz & 1;             // which 64-row half of queries
    const int tid  = threadIdx.x;
    const int warp = tid >> 5;         // 0..3
    const int lane = tid & 31;
    const int lr   = lane >> 2;
    const int lc   = lane & 3;
    const int m0   = warp * 16;        // local query row base (0..48)

    const int tb    = b * PS + c * PW;
    const int qrow0 = qh * 64;         // CTA query offset within chunk
    const int cbase = h * PHD;

    // ---- Load Q (64 rows) with fused RoPE ----
#pragma unroll
    for (int l = 0; l < 8; l++) {
        int f  = tid + l * 128;            // 0..1023 = 64 rows x 16 chunks
        int r  = f >> 4;                   // local 0..63
        int d4 = (f & 15) << 2;            // 0..60
        int gr = qrow0 + r;                // row in chunk 0..127
        size_t g0 = (size_t)(tb + gr) * PD3 + cbase + d4;
        uint2 uqa = *(const uint2*)&QKV[g0];
        uint2 uqb = *(const uint2*)&QKV[g0 + 64];
        float2 qa01 = __half22float2(*(__half2*)&uqa.x);
        float2 qa23 = __half22float2(*(__half2*)&uqa.y);
        float2 qb01 = __half22float2(*(__half2*)&uqb.x);
        float2 qb23 = __half22float2(*(__half2*)&uqb.y);
        float4 cv = *(const float4*)&ctab[gr * 64 + d4];
        float4 sv = *(const float4*)&stab[gr * 64 + d4];
        __half2 h0, h1; uint2 u;
        h0 = __floats2half2_rn(qa01.x * cv.x - qb01.x * sv.x,
                               qa01.y * cv.y - qb01.y * sv.y);
        h1 = __floats2half2_rn(qa23.x * cv.z - qb23.x * sv.z,
                               qa23.y * cv.w - qb23.y * sv.w);
        u.x = *(uint32_t*)&h0; u.y = *(uint32_t*)&h1;
        *(uint2*)&sQ[r * AST + d4] = u;
        h0 = __floats2half2_rn(qb01.x * cv.x + qa01.x * sv.x,
                               qb01.y * cv.y + qa01.y * sv.y);
        h1 = __floats2half2_rn(qb23.x * cv.z + qa23.x * sv.z,
                               qb23.y * cv.w + qa23.y * sv.w);
        u.x = *(uint32_t*)&h0; u.y = *(uint32_t*)&h1;
        *(uint2*)&sQ[r * AST + d4 + 64] = u;
    }
    // ---- Load K (128 rows) with fused RoPE ----
#pragma unroll
    for (int l = 0; l < 16; l++) {
        int f  = tid + l * 128;            // 0..2047 = 128 rows x 16 chunks
        int r  = f >> 4;
        int d4 = (f & 15) << 2;
        size_t g0 = (size_t)(tb + r) * PD3 + cbase + PD + d4;
        uint2 uka = *(const uint2*)&QKV[g0];
        uint2 ukb = *(const uint2*)&QKV[g0 + 64];
        float2 ka01 = __half22float2(*(__half2*)&uka.x);
        float2 ka23 = __half22float2(*(__half2*)&uka.y);
        float2 kb01 = __half22float2(*(__half2*)&ukb.x);
        float2 kb23 = __half22float2(*(__half2*)&ukb.y);
        float4 cv = *(const float4*)&ctab[r * 64 + d4];
        float4 sv = *(const float4*)&stab[r * 64 + d4];
        __half2 h0, h1; uint2 u;
        h0 = __floats2half2_rn(ka01.x * cv.x - kb01.x * sv.x,
                               ka01.y * cv.y - kb01.y * sv.y);
        h1 = __floats2half2_rn(ka23.x * cv.z - kb23.x * sv.z,
                               ka23.y * cv.w - kb23.y * sv.w);
        u.x = *(uint32_t*)&h0; u.y = *(uint32_t*)&h1;
        *(uint2*)&sK[r * AST + d4] = u;
        h0 = __floats2half2_rn(kb01.x * cv.x + ka01.x * sv.x,
                               kb01.y * cv.y + ka01.y * sv.y);
        h1 = __floats2half2_rn(kb23.x * cv.z + ka23.x * sv.z,
                               kb23.y * cv.w + ka23.y * sv.w);
        u.x = *(uint32_t*)&h0; u.y = *(uint32_t*)&h1;
        *(uint2*)&sK[r * AST + d4 + 64] = u;
    }
    // ---- Load V (128 rows, straight copy) ----
#pragma unroll
    for (int l = 0; l < 16; l++) {
        int f  = tid + l * 128;            // 0..2047 = 128 rows x 16 chunks(8h)
        int r  = f >> 4;
        int d4 = (f & 15) << 3;
        uint4 uv = *(const uint4*)&QKV[(size_t)(tb + r) * PD3 + cbase + 2 * PD + d4];
        *(uint4*)&sV[r * AST + d4] = uv;
    }
    __syncthreads();

    // ---- Phase 1: S = Q K^T (16 rows x 128 cols per warp) ----
    float sacc[16][4];
#pragma unroll
    for (int i = 0; i < 16; i++)
#pragma unroll
        for (int j = 0; j < 4; j++) sacc[i][j] = 0.0f;

    const int a_r = m0 + (lane & 15);
    const int a_c = (lane >> 4) * 8;
    const int b_r = (lane & 7) + (lane >> 4) * 8;
    const int b_c = ((lane >> 3) & 1) * 8;

#pragma unroll
    for (int ks = 0; ks < 8; ks++) {
        const int kb = ks * 16;
        uint32_t af[4];
        ldsm_x4(af, (uint32_t)__cvta_generic_to_shared(sQ + a_r * AST + kb + a_c));
#pragma unroll
        for (int p = 0; p < 8; p++) {
            uint32_t bf[4];
            ldsm_x4(bf, (uint32_t)__cvta_generic_to_shared(
                        sK + (p * 16 + b_r) * AST + kb + b_c));
            mma_f16(sacc[2 * p    ], af, bf);
            mma_f16(sacc[2 * p + 1], af, bf + 2);
        }
    }

    const float scale = 0.08838834764831845f;
    const float NEG = -3.402823466e38f;
    const float* mrow0 = mask + (size_t)b * PS * PS
                       + (size_t)(c * PW + qrow0 + m0 + lr) * PS + c * PW;
    const float* mrow1 = mrow0 + 8 * PS;
#pragma unroll
    for (int nt = 0; nt < 16; nt++) {
        float2 mv0 = *(const float2*)&mrow0[nt * 8 + 2 * lc];
        float2 mv1 = *(const float2*)&mrow1[nt * 8 + 2 * lc];
        sacc[nt][0] = fmaxf(fmaf(sacc[nt][0], scale, mv0.x), NEG);
        sacc[nt][1] = fmaxf(fmaf(sacc[nt][1], scale, mv0.y), NEG);
        sacc[nt][2] = fmaxf(fmaf(sacc[nt][2], scale, mv1.x), NEG);
        sacc[nt][3] = fmaxf(fmaf(sacc[nt][3], scale, mv1.y), NEG);
    }

    // ---- softmax ----
    float mx0 = -FLT_MAX, mx1 = -FLT_MAX;
#pragma unroll
    for (int nt = 0; nt < 16; nt++) {
        mx0 = fmaxf(mx0, fmaxf(sacc[nt][0], sacc[nt][1]));
        mx1 = fmaxf(mx1, fmaxf(sacc[nt][2], sacc[nt][3]));
    }
    mx0 = fmaxf(mx0, __shfl_xor_sync(0xFFFFFFFF, mx0, 1));
    mx0 = fmaxf(mx0, __shfl_xor_sync(0xFFFFFFFF, mx0, 2));
    mx1 = fmaxf(mx1, __shfl_xor_sync(0xFFFFFFFF, mx1, 1));
    mx1 = fmaxf(mx1, __shfl_xor_sync(0xFFFFFFFF, mx1, 2));

    float sum0 = 0.f, sum1 = 0.f;
#pragma unroll
    for (int nt = 0; nt < 16; nt++) {
        sacc[nt][0] = __expf(sacc[nt][0] - mx0);
        sacc[nt][1] = __expf(sacc[nt][1] - mx0);
        sacc[nt][2] = __expf(sacc[nt][2] - mx1);
        sacc[nt][3] = __expf(sacc[nt][3] - mx1);
        sum0 += sacc[nt][0] + sacc[nt][1];
        sum1 += sacc[nt][2] + sacc[nt][3];
    }
    sum0 += __shfl_xor_sync(0xFFFFFFFF, sum0, 1);
    sum0 += __shfl_xor_sync(0xFFFFFFFF, sum0, 2);
    sum1 += __shfl_xor_sync(0xFFFFFFFF, sum1, 1);
    sum1 += __shfl_xor_sync(0xFFFFFFFF, sum1, 2);
    const float inv0 = 1.0f / sum0;
    const float inv1 = 1.0f / sum1;

    uint32_t pf[8][4];
#pragma unroll
    for (int ks = 0; ks < 8; ks++) {
        __half2 p0 = __floats2half2_rn(sacc[2 * ks][0] * inv0, sacc[2 * ks][1] * inv0);
        __half2 p1 = __floats2half2_rn(sacc[2 * ks][2] * inv1, sacc[2 * ks][3] * inv1);
        __half2 p2 = __floats2half2_rn(sacc[2 * ks + 1][0] * inv0, sacc[2 * ks + 1][1] * inv0);
        __half2 p3 = __floats2half2_rn(sacc[2 * ks + 1][2] * inv1, sacc[2 * ks + 1][3] * inv1);
        pf[ks][0] = *(uint32_t*)&p0;
        pf[ks][1] = *(uint32_t*)&p1;
        pf[ks][2] = *(uint32_t*)&p2;
        pf[ks][3] = *(uint32_t*)&p3;
    }

    // ---- Phase 2: O = P V ----
    float oacc[16][4];
#pragma unroll
    for (int i = 0; i < 16; i++)
#pragma unroll
        for (int j = 0; j < 4; j++) oacc[i][j] = 0.0f;

    const int v_r = (lane & 15);
    const int v_c = (lane >> 4) * 8;
#pragma unroll
    for (int ks = 0; ks < 8; ks++) {
        const int kb = ks * 16;
#pragma unroll
        for (int p = 0; p < 8; p++) {
            uint32_t bf[4];
            ldsm_x4_t(bf, (uint32_t)__cvta_generic_to_shared(
                          sV + (kb + v_r) * AST + p * 16 + v_c));
            mma_f16(oacc[2 * p    ], pf[ks], bf);
            mma_f16(oacc[2 * p + 1], pf[ks], bf + 2);
        }
    }

#pragma unroll
    for (int nt = 0; nt < 16; nt++) {
        int col = cbase + nt * 8 + 2 * lc;
        size_t g0 = (size_t)(tb + qrow0 + m0 + lr    ) * PD + col;
        size_t g1 = (size_t)(tb + qrow0 + m0 + lr + 8) * PD + col;
        __half2 o0 = __floats2half2_rn(oacc[nt][0], oacc[nt][1]);
        __half2 o1 = __floats2half2_rn(oacc[nt][2], oacc[nt][3]);
        *(uint32_t*)&O[g0] = *(uint32_t*)&o0;
        *(uint32_t*)&O[g1] = *(uint32_t*)&o1;
    }
}

// ---------------------------------------------------------------------------
extern "C" void kernel_launch(void* const* d_in, const int* in_sizes, int n_in,
                              void* d_out, int out_size)
{
    const float* x    = (const float*)d_in[0];
    const float* mask = (const float*)d_in[1];
    const float* wq   = (const float*)d_in[2];
    const float* wk   = (const float*)d_in[3];
    const float* wv   = (const float*)d_in[4];
    const float* wo   = (const float*)d_in[5];
    float* out = (float*)d_out;

    void *pqkv, *pxh, *pwh, *paoh, *pct, *pst;
    cudaGetSymbolAddress(&pqkv, g_qkv);
    cudaGetSymbolAddress(&pxh,  g_xh);
    cudaGetSymbolAddress(&pwh,  g_wh);
    cudaGetSymbolAddress(&paoh, g_aoh);
    cudaGetSymbolAddress(&pct,  g_cos);
    cudaGetSymbolAddress(&pst,  g_sin);
    __half* qkv  = (__half*)pqkv;
    __half* xh   = (__half*)pxh;
    __half* wh   = (__half*)pwh;
    __half* aoh  = (__half*)paoh;
    float*  ctab = (float*)pct;
    float*  stab = (float*)pst;

    // Fused prep + rope tables
    {
        int n4 = N4X + 4 * N4W;              // 8,388,608
        prep_kernel<<<n4 / 256, 256>>>((const float4*)x,
                                       (const float4*)wq, (const float4*)wk,
                                       (const float4*)wv, (const float4*)wo,
                                       xh, wh);
        rope_table_kernel<<<(PW * 64) / 256, 256>>>(ctab, stab);
    }

    size_t gsmem = (size_t)2 * NST * STG * sizeof(__half);   // 110,592 B
    cudaFuncSetAttribute(gemm_f16<__half>, cudaFuncAttributeMaxDynamicSharedMemorySize,
                         (int)gsmem);
    cudaFuncSetAttribute(gemm_f16<float>, cudaFuncAttributeMaxDynamicSharedMemorySize,
                         (int)gsmem);

    // Fused QKV projection: [8192 x 2048] x [6144 x 2048]^T -> fp16 [8192 x 6144]
    dim3 gqkv(PD3 / BN, PT / BM);            // 48 x 64
    gemm_f16<__half><<<gqkv, 128, gsmem>>>(xh, wh, qkv, PT, PD3, PD);

    // Attention (rope fused in loader); 2 CTAs per (c,h,b), 64 q-rows each
    size_t asmem = (size_t)(64 + 128 + 128) * AST * sizeof(__half);  // 87,040 B
    cudaFuncSetAttribute(attn_mma, cudaFuncAttributeMaxDynamicSharedMemorySize,
                         (int)asmem);
    attn_mma<<<dim3(PNC, PH, PB * 2), 128, asmem>>>(qkv, mask, ctab, stab, aoh);

    // Output projection (fp32 out)
    dim3 gout(PD / BN, PT / BM);             // 16 x 64
    gemm_f16<float><<<gout, 128, gsmem>>>(aoh, wh + 3 * (size_t)PD * PD, out, PT, PD, PD);
}

// round 13
// speedup vs baseline: 1.1083x; 1.0197x over previous
#include <cuda_runtime.h>
#include <cuda_fp16.h>
#include <math.h>
#include <float.h>
#include <stdint.h>

// Problem constants
#define PB 2
#define PS 4096
#define PD 2048
#define PD3 6144              // fused QKV output width
#define PH 16
#define PHD 128
#define PW 128
#define PNC 32
#define PT (PB*PS)            // 8192 tokens

// Scratch (allocation-free)
__device__ __half g_qkv[PT * PD3];              // fused fp16 Q|K|V
__device__ __half g_xh [PT * PD];               // fp16 x
__device__ __half g_wh [4 * (size_t)PD * PD];   // fp16 wq,wk,wv,wo (concat)
__device__ __half g_aoh[PT * PD];               // fp16 attention output
__device__ float  g_cos[PW * 64];               // rope tables
__device__ float  g_sin[PW * 64];

// ---------------------------------------------------------------------------
// PTX helpers
// ---------------------------------------------------------------------------
__device__ __forceinline__ void cp_async16(uint32_t saddr, const void* gptr) {
    asm volatile("cp.async.cg.shared.global [%0], [%1], 16;\n" :: "r"(saddr), "l"(gptr));
}
__device__ __forceinline__ void mma_f16(float* c, const uint32_t* a, const uint32_t* b) {
    asm volatile(
        "mma.sync.aligned.m16n8k16.row.col.f32.f16.f16.f32 "
        "{%0,%1,%2,%3}, {%4,%5,%6,%7}, {%8,%9}, {%0,%1,%2,%3};"
        : "+f"(c[0]), "+f"(c[1]), "+f"(c[2]), "+f"(c[3])
        : "r"(a[0]), "r"(a[1]), "r"(a[2]), "r"(a[3]), "r"(b[0]), "r"(b[1]));
}
__device__ __forceinline__ void ldsm_x4(uint32_t* r, uint32_t addr) {
    asm volatile("ldmatrix.sync.aligned.m8n8.x4.shared.b16 {%0,%1,%2,%3}, [%4];"
        : "=r"(r[0]), "=r"(r[1]), "=r"(r[2]), "=r"(r[3]) : "r"(addr));
}
__device__ __forceinline__ void ldsm_x4_t(uint32_t* r, uint32_t addr) {
    asm volatile("ldmatrix.sync.aligned.m8n8.x4.trans.shared.b16 {%0,%1,%2,%3}, [%4];"
        : "=r"(r[0]), "=r"(r[1]), "=r"(r[2]), "=r"(r[3]) : "r"(addr));
}

// ---------------------------------------------------------------------------
// fp16 tensor-core GEMM (R9 config — best measured): C = A * W^T, fp32 acc.
// CTA 128x128, BK=64 halves, 256 threads = 8 warps (2m x 4n), warp tile 64x32.
// 3-stage circular cp.async pipeline, ldmatrix fragments, m16n8k16. 2 CTAs/SM.
// ---------------------------------------------------------------------------
#define BM 128
#define BN 128
#define BKH 64
#define KST 72                 // BKH + 8 pad (144B rows; ldmatrix conflict-free)
#define NST 3

template <typename OutT>
__global__ __launch_bounds__(256, 2)
void gemm_f16(const __half* __restrict__ A, const __half* __restrict__ W,
              OutT* __restrict__ C, int M, int N, int K)
{
    extern __shared__ __half smh[];
    __half* sA = smh;                        // [3][128][72]
    __half* sB = smh + NST * BM * KST;

    const int tid  = threadIdx.x;
    const int bm   = blockIdx.y * BM;
    const int bn   = blockIdx.x * BN;
    const int warp = tid >> 5;
    const int lane = tid & 31;
    const int wm   = (warp & 1) * 64;
    const int wn   = (warp >> 1) * 32;
    const int lr   = lane >> 2;
    const int lc   = lane & 3;

    float acc[4][4][4];
#pragma unroll
    for (int i = 0; i < 4; i++)
#pragma unroll
        for (int j = 0; j < 4; j++)
#pragma unroll
            for (int r = 0; r < 4; r++) acc[i][j][r] = 0.0f;

    const int T = K / BKH;                   // 32

    auto load_tile = [&](int t, int buf) {
        const int k0 = t * BKH;
        __half* a_dst = sA + buf * BM * KST;
        __half* b_dst = sB + buf * BM * KST;
#pragma unroll
        for (int i = 0; i < 8; i++) {
            int c   = tid + i * 256;
            int isB = c >> 10;
            int idx = c & 1023;
            int r   = idx >> 3;
            int c8  = (idx & 7) * 8;
            const __half* g = isB ? &W[(size_t)(bn + r) * K + k0 + c8]
                                  : &A[(size_t)(bm + r) * K + k0 + c8];
            __half* d = (isB ? b_dst : a_dst) + r * KST + c8;
            cp_async16((uint32_t)__cvta_generic_to_shared(d), g);
        }
        asm volatile("cp.async.commit_group;\n");
    };

    load_tile(0, 0);
    load_tile(1, 1);

    const int a_r = (lane & 15);
    const int a_c = (lane >> 4) * 8;
    const int b_r = (lane & 7) + (lane >> 4) * 8;
    const int b_c = ((lane >> 3) & 1) * 8;

    int buf = 0;
    for (int t = 0; t < T; t++) {
        if (t < T - 1) { asm volatile("cp.async.wait_group 1;\n"); }
        else           { asm volatile("cp.async.wait_group 0;\n"); }
        __syncthreads();

        if (t + 2 < T) {
            int nb = buf + 2; if (nb >= NST) nb -= NST;
            load_tile(t + 2, nb);
        }

        const __half* a_s = sA + buf * BM * KST;
        const __half* b_s = sB + buf * BM * KST;

#pragma unroll
        for (int kk = 0; kk < 4; kk++) {
            const int kb = kk * 16;
            uint32_t af[4][4];
#pragma unroll
            for (int mt = 0; mt < 4; mt++) {
                uint32_t ad = (uint32_t)__cvta_generic_to_shared(
                    a_s + (wm + mt * 16 + a_r) * KST + kb + a_c);
                ldsm_x4(af[mt], ad);
            }
            uint32_t bf[2][4];
#pragma unroll
            for (int p = 0; p < 2; p++) {
                uint32_t bd = (uint32_t)__cvta_generic_to_shared(
                    b_s + (wn + p * 16 + b_r) * KST + kb + b_c);
                ldsm_x4(bf[p], bd);
            }
#pragma unroll
            for (int mt = 0; mt < 4; mt++)
#pragma unroll
                for (int nt = 0; nt < 4; nt++)
                    mma_f16(acc[mt][nt], af[mt], &bf[nt >> 1][(nt & 1) * 2]);
        }
        buf++; if (buf == NST) buf = 0;
    }

#pragma unroll
    for (int mt = 0; mt < 4; mt++) {
#pragma unroll
        for (int nt = 0; nt < 4; nt++) {
            int r0 = bm + wm + mt * 16 + lr;
            int cc = bn + wn + nt * 8 + 2 * lc;
            if (sizeof(OutT) == 4) {
                float* Cf = (float*)C;
                *(float2*)&Cf[(size_t)(r0    ) * N + cc] = make_float2(acc[mt][nt][0], acc[mt][nt][1]);
                *(float2*)&Cf[(size_t)(r0 + 8) * N + cc] = make_float2(acc[mt][nt][2], acc[mt][nt][3]);
            } else {
                __half* Ch = (__half*)C;
                __half2 h0 = __floats2half2_rn(acc[mt][nt][0], acc[mt][nt][1]);
                __half2 h1 = __floats2half2_rn(acc[mt][nt][2], acc[mt][nt][3]);
                *(uint32_t*)&Ch[(size_t)(r0    ) * N + cc] = *(uint32_t*)&h0;
                *(uint32_t*)&Ch[(size_t)(r0 + 8) * N + cc] = *(uint32_t*)&h1;
            }
        }
    }
}

// ---------------------------------------------------------------------------
// Fused prep with MLP=2: thread i converts x-chunk i AND weight-chunk i.
// ---------------------------------------------------------------------------
#define N4X (PT * PD / 4)          // 4,194,304
#define N4W (PD * PD / 4)          // 1,048,576

__global__ void prep_kernel(const float4* __restrict__ x,
                            const float4* __restrict__ w0, const float4* __restrict__ w1,
                            const float4* __restrict__ w2, const float4* __restrict__ w3,
                            __half* __restrict__ xh, __half* __restrict__ wh)
{
    int i = blockIdx.x * blockDim.x + threadIdx.x;
    if (i >= N4X) return;
    int sel = i >> 20;                        // i / N4W  (4*N4W == N4X)
    int rem = i & (N4W - 1);
    const float4* s = (sel == 0) ? w0 : (sel == 1) ? w1 : (sel == 2) ? w2 : w3;
    float4 v1 = x[i];
    float4 v2 = s[rem];

    __half2 a0 = __floats2half2_rn(v1.x, v1.y);
    __half2 a1 = __floats2half2_rn(v1.z, v1.w);
    uint2 o1; o1.x = *(uint32_t*)&a0; o1.y = *(uint32_t*)&a1;
    *(uint2*)&xh[(size_t)i * 4] = o1;

    __half2 b0 = __floats2half2_rn(v2.x, v2.y);
    __half2 b1 = __floats2half2_rn(v2.z, v2.w);
    uint2 o2; o2.x = *(uint32_t*)&b0; o2.y = *(uint32_t*)&b1;
    *(uint2*)&wh[(size_t)i * 4] = o2;
}

// ---------------------------------------------------------------------------
// RoPE cos/sin tables
// ---------------------------------------------------------------------------
__global__ void rope_table_kernel(float* __restrict__ ct, float* __restrict__ st)
{
    int t = blockIdx.x * blockDim.x + threadIdx.x;
    if (t >= PW * 64) return;
    int w = t >> 6;
    int j = t & 63;
    const float c_ln = 9.210340371976184f / 64.0f;
    float freq = (float)w * expf(-(float)j * c_ln);
    ct[t] = cosf(freq);
    st[t] = sinf(freq);
}

// ---------------------------------------------------------------------------
// Tensor-core block-local attention: fused RoPE, fp16 QKV input, and the
// fp32 mask tile prefetched into smem via cp.async (overlaps DRAM latency
// with QKV load + S-phase MMAs). One CTA per (chunk, head, batch), 8 warps.
// ---------------------------------------------------------------------------
#define AST 136                 // QKV smem row stride in halves (272B)
#define MST 132                 // mask smem row stride in floats (528B)

__global__ __launch_bounds__(256, 1)
void attn_mma(const __half* __restrict__ QKV, const float* __restrict__ mask,
              const float* __restrict__ ctab, const float* __restrict__ stab,
              __half* __restrict__ O)
{
    extern __shared__ __half sh[];
    __half* sQ = sh;                   // [128][136]
    __half* sK = sh + 128 * AST;
    __half* sV = sh + 2 * 128 * AST;
    float*  sM = (float*)(sh + 3 * 128 * AST);   // [128][132] fp32

    const int c = blockIdx.x;
    const int h = blockIdx.y;
    const int b = blockIdx.z;
    const int tid  = threadIdx.x;
    const int warp = tid >> 5;
    const int lane = tid & 31;
    const int lr   = lane >> 2;
    const int lc   = lane & 3;
    const int m0   = warp * 16;

    const int tb    = b * PS + c * PW;
    const int cbase = h * PHD;

    // ---- Kick off mask prefetch FIRST (64KB, 16 cp.async per thread) ----
    {
        const float* mg = mask + (size_t)b * PS * PS + (size_t)(c * PW) * PS + c * PW;
#pragma unroll
        for (int l = 0; l < 16; l++) {
            int f  = tid + l * 256;        // 0..4095
            int r  = f >> 5;               // 0..127
            int c4 = (f & 31) * 4;         // float col 0..124
            cp_async16((uint32_t)__cvta_generic_to_shared(&sM[r * MST + c4]),
                       mg + (size_t)r * PS + c4);
        }
        asm volatile("cp.async.commit_group;\n");
    }

    // ---- Load Q,K with fused RoPE (fp16 source; pairs d and d+64) ----
#pragma unroll
    for (int l = 0; l < 8; l++) {
        int f  = tid + l * 256;            // 0..2047 = 128 rows x 16 chunks
        int r  = f >> 4;
        int d4 = (f & 15) << 2;            // 0..60
        size_t g0 = (size_t)(tb + r) * PD3 + cbase + d4;
        uint2 uqa = *(const uint2*)&QKV[g0];
        uint2 uqb = *(const uint2*)&QKV[g0 + 64];
        uint2 uka = *(const uint2*)&QKV[g0 + PD];
        uint2 ukb = *(const uint2*)&QKV[g0 + PD + 64];
        float2 qa01 = __half22float2(*(__half2*)&uqa.x);
        float2 qa23 = __half22float2(*(__half2*)&uqa.y);
        float2 qb01 = __half22float2(*(__half2*)&uqb.x);
        float2 qb23 = __half22float2(*(__half2*)&uqb.y);
        float2 ka01 = __half22float2(*(__half2*)&uka.x);
        float2 ka23 = __half22float2(*(__half2*)&uka.y);
        float2 kb01 = __half22float2(*(__half2*)&ukb.x);
        float2 kb23 = __half22float2(*(__half2*)&ukb.y);
        float4 cv = *(const float4*)&ctab[r * 64 + d4];
        float4 sv = *(const float4*)&stab[r * 64 + d4];

        __half2 h0, h1;
        uint2 u;
        h0 = __floats2half2_rn(qa01.x * cv.x - qb01.x * sv.x,
                               qa01.y * cv.y - qb01.y * sv.y);
        h1 = __floats2half2_rn(qa23.x * cv.z - qb23.x * sv.z,
                               qa23.y * cv.w - qb23.y * sv.w);
        u.x = *(uint32_t*)&h0; u.y = *(uint32_t*)&h1;
        *(uint2*)&sQ[r * AST + d4] = u;
        h0 = __floats2half2_rn(qb01.x * cv.x + qa01.x * sv.x,
                               qb01.y * cv.y + qa01.y * sv.y);
        h1 = __floats2half2_rn(qb23.x * cv.z + qa23.x * sv.z,
                               qb23.y * cv.w + qa23.y * sv.w);
        u.x = *(uint32_t*)&h0; u.y = *(uint32_t*)&h1;
        *(uint2*)&sQ[r * AST + d4 + 64] = u;
        h0 = __floats2half2_rn(ka01.x * cv.x - kb01.x * sv.x,
                               ka01.y * cv.y - kb01.y * sv.y);
        h1 = __floats2half2_rn(ka23.x * cv.z - kb23.x * sv.z,
                               ka23.y * cv.w - kb23.y * sv.w);
        u.x = *(uint32_t*)&h0; u.y = *(uint32_t*)&h1;
        *(uint2*)&sK[r * AST + d4] = u;
        h0 = __floats2half2_rn(kb01.x * cv.x + ka01.x * sv.x,
                               kb01.y * cv.y + ka01.y * sv.y);
        h1 = __floats2half2_rn(kb23.x * cv.z + ka23.x * sv.z,
                               kb23.y * cv.w + ka23.y * sv.w);
        u.x = *(uint32_t*)&h0; u.y = *(uint32_t*)&h1;
        *(uint2*)&sK[r * AST + d4 + 64] = u;
    }
    // ---- Load V (fp16, straight copy) ----
#pragma unroll
    for (int l = 0; l < 8; l++) {
        int f  = tid + l * 256;
        int r  = f >> 4;
        int d4 = (f & 15) << 3;            // 8-half chunks
        uint4 uv = *(const uint4*)&QKV[(size_t)(tb + r) * PD3 + cbase + 2 * PD + d4];
        *(uint4*)&sV[r * AST + d4] = uv;
    }
    __syncthreads();

    // ---- Phase 1: S = Q K^T ----
    float sacc[16][4];
#pragma unroll
    for (int i = 0; i < 16; i++)
#pragma unroll
        for (int j = 0; j < 4; j++) sacc[i][j] = 0.0f;

    const int a_r = m0 + (lane & 15);
    const int a_c = (lane >> 4) * 8;
    const int b_r = (lane & 7) + (lane >> 4) * 8;
    const int b_c = ((lane >> 3) & 1) * 8;

#pragma unroll
    for (int ks = 0; ks < 8; ks++) {
        const int kb = ks * 16;
        uint32_t af[4];
        ldsm_x4(af, (uint32_t)__cvta_generic_to_shared(sQ + a_r * AST + kb + a_c));
#pragma unroll
        for (int p = 0; p < 8; p++) {
            uint32_t bf[4];
            ldsm_x4(bf, (uint32_t)__cvta_generic_to_shared(
                        sK + (p * 16 + b_r) * AST + kb + b_c));
            mma_f16(sacc[2 * p    ], af, bf);
            mma_f16(sacc[2 * p + 1], af, bf + 2);
        }
    }

    // ---- mask from smem (prefetched) ----
    asm volatile("cp.async.wait_group 0;\n");
    __syncthreads();

    const float scale = 0.08838834764831845f;
    const float NEG = -3.402823466e38f;
    const float* mrow0 = &sM[(m0 + lr) * MST];
    const float* mrow1 = mrow0 + 8 * MST;
#pragma unroll
    for (int nt = 0; nt < 16; nt++) {
        float2 mv0 = *(const float2*)&mrow0[nt * 8 + 2 * lc];
        float2 mv1 = *(const float2*)&mrow1[nt * 8 + 2 * lc];
        sacc[nt][0] = fmaxf(fmaf(sacc[nt][0], scale, mv0.x), NEG);
        sacc[nt][1] = fmaxf(fmaf(sacc[nt][1], scale, mv0.y), NEG);
        sacc[nt][2] = fmaxf(fmaf(sacc[nt][2], scale, mv1.x), NEG);
        sacc[nt][3] = fmaxf(fmaf(sacc[nt][3], scale, mv1.y), NEG);
    }

    // ---- softmax ----
    float mx0 = -FLT_MAX, mx1 = -FLT_MAX;
#pragma unroll
    for (int nt = 0; nt < 16; nt++) {
        mx0 = fmaxf(mx0, fmaxf(sacc[nt][0], sacc[nt][1]));
        mx1 = fmaxf(mx1, fmaxf(sacc[nt][2], sacc[nt][3]));
    }
    mx0 = fmaxf(mx0, __shfl_xor_sync(0xFFFFFFFF, mx0, 1));
    mx0 = fmaxf(mx0, __shfl_xor_sync(0xFFFFFFFF, mx0, 2));
    mx1 = fmaxf(mx1, __shfl_xor_sync(0xFFFFFFFF, mx1, 1));
    mx1 = fmaxf(mx1, __shfl_xor_sync(0xFFFFFFFF, mx1, 2));

    float sum0 = 0.f, sum1 = 0.f;
#pragma unroll
    for (int nt = 0; nt < 16; nt++) {
        sacc[nt][0] = __expf(sacc[nt][0] - mx0);
        sacc[nt][1] = __expf(sacc[nt][1] - mx0);
        sacc[nt][2] = __expf(sacc[nt][2] - mx1);
        sacc[nt][3] = __expf(sacc[nt][3] - mx1);
        sum0 += sacc[nt][0] + sacc[nt][1];
        sum1 += sacc[nt][2] + sacc[nt][3];
    }
    sum0 += __shfl_xor_sync(0xFFFFFFFF, sum0, 1);
    sum0 += __shfl_xor_sync(0xFFFFFFFF, sum0, 2);
    sum1 += __shfl_xor_sync(0xFFFFFFFF, sum1, 1);
    sum1 += __shfl_xor_sync(0xFFFFFFFF, sum1, 2);
    const float inv0 = 1.0f / sum0;
    const float inv1 = 1.0f / sum1;

    uint32_t pf[8][4];
#pragma unroll
    for (int ks = 0; ks < 8; ks++) {
        __half2 p0 = __floats2half2_rn(sacc[2 * ks][0] * inv0, sacc[2 * ks][1] * inv0);
        __half2 p1 = __floats2half2_rn(sacc[2 * ks][2] * inv1, sacc[2 * ks][3] * inv1);
        __half2 p2 = __floats2half2_rn(sacc[2 * ks + 1][0] * inv0, sacc[2 * ks + 1][1] * inv0);
        __half2 p3 = __floats2half2_rn(sacc[2 * ks + 1][2] * inv1, sacc[2 * ks + 1][3] * inv1);
        pf[ks][0] = *(uint32_t*)&p0;
        pf[ks][1] = *(uint32_t*)&p1;
        pf[ks][2] = *(uint32_t*)&p2;
        pf[ks][3] = *(uint32_t*)&p3;
    }

    // ---- Phase 2: O = P V ----
    float oacc[16][4];
#pragma unroll
    for (int i = 0; i < 16; i++)
#pragma unroll
        for (int j = 0; j < 4; j++) oacc[i][j] = 0.0f;

    const int v_r = (lane & 15);
    const int v_c = (lane >> 4) * 8;
#pragma unroll
    for (int ks = 0; ks < 8; ks++) {
        const int kb = ks * 16;
#pragma unroll
        for (int p = 0; p < 8; p++) {
            uint32_t bf[4];
            ldsm_x4_t(bf, (uint32_t)__cvta_generic_to_shared(
                          sV + (kb + v_r) * AST + p * 16 + v_c));
            mma_f16(oacc[2 * p    ], pf[ks], bf);
            mma_f16(oacc[2 * p + 1], pf[ks], bf + 2);
        }
    }

#pragma unroll
    for (int nt = 0; nt < 16; nt++) {
        int col = cbase + nt * 8 + 2 * lc;
        size_t g0 = (size_t)(tb + m0 + lr    ) * PD + col;
        size_t g1 = (size_t)(tb + m0 + lr + 8) * PD + col;
        __half2 o0 = __floats2half2_rn(oacc[nt][0], oacc[nt][1]);
        __half2 o1 = __floats2half2_rn(oacc[nt][2], oacc[nt][3]);
        *(uint32_t*)&O[g0] = *(uint32_t*)&o0;
        *(uint32_t*)&O[g1] = *(uint32_t*)&o1;
    }
}

// ---------------------------------------------------------------------------
extern "C" void kernel_launch(void* const* d_in, const int* in_sizes, int n_in,
                              void* d_out, int out_size)
{
    const float* x    = (const float*)d_in[0];
    const float* mask = (const float*)d_in[1];
    const float* wq   = (const float*)d_in[2];
    const float* wk   = (const float*)d_in[3];
    const float* wv   = (const float*)d_in[4];
    const float* wo   = (const float*)d_in[5];
    float* out = (float*)d_out;

    void *pqkv, *pxh, *pwh, *paoh, *pct, *pst;
    cudaGetSymbolAddress(&pqkv, g_qkv);
    cudaGetSymbolAddress(&pxh,  g_xh);
    cudaGetSymbolAddress(&pwh,  g_wh);
    cudaGetSymbolAddress(&paoh, g_aoh);
    cudaGetSymbolAddress(&pct,  g_cos);
    cudaGetSymbolAddress(&pst,  g_sin);
    __half* qkv  = (__half*)pqkv;
    __half* xh   = (__half*)pxh;
    __half* wh   = (__half*)pwh;
    __half* aoh  = (__half*)paoh;
    float*  ctab = (float*)pct;
    float*  stab = (float*)pst;

    // Fused prep (MLP=2) + rope tables
    prep_kernel<<<N4X / 256, 256>>>((const float4*)x,
                                    (const float4*)wq, (const float4*)wk,
                                    (const float4*)wv, (const float4*)wo,
                                    xh, wh);
    rope_table_kernel<<<(PW * 64) / 256, 256>>>(ctab, stab);

    size_t gsmem = (size_t)2 * NST * BM * KST * sizeof(__half);   // 110,592 B
    cudaFuncSetAttribute(gemm_f16<__half>, cudaFuncAttributeMaxDynamicSharedMemorySize,
                         (int)gsmem);
    cudaFuncSetAttribute(gemm_f16<float>, cudaFuncAttributeMaxDynamicSharedMemorySize,
                         (int)gsmem);

    // Fused QKV projection: [8192 x 2048] x [6144 x 2048]^T -> fp16 [8192 x 6144]
    dim3 gqkv(PD3 / BN, PT / BM);            // 48 x 64
    gemm_f16<__half><<<gqkv, 256, gsmem>>>(xh, wh, qkv, PT, PD3, PD);

    // Attention (rope fused; mask prefetched to smem)
    size_t asmem = (size_t)3 * 128 * AST * sizeof(__half)
                 + (size_t)128 * MST * sizeof(float);   // 104,448 + 67,584 = 172,032 B
    cudaFuncSetAttribute(attn_mma, cudaFuncAttributeMaxDynamicSharedMemorySize,
                         (int)asmem);
    attn_mma<<<dim3(PNC, PH, PB), 256, asmem>>>(qkv, mask, ctab, stab, aoh);

    // Output projection (fp32 out)
    dim3 gout(PD / BN, PT / BM);             // 16 x 64
    gemm_f16<float><<<gout, 256, gsmem>>>(aoh, wh + 3 * (size_t)PD * PD, out, PT, PD, PD);
}

// round 14
// speedup vs baseline: 1.1128x; 1.0041x over previous
#include <cuda_runtime.h>
#include <cuda_fp16.h>
#include <math.h>
#include <float.h>
#include <stdint.h>

// Problem constants
#define PB 2
#define PS 4096
#define PD 2048
#define PD3 6144              // fused QKV output width
#define PH 16
#define PHD 128
#define PW 128
#define PNC 32
#define PT (PB*PS)            // 8192 tokens

// Scratch (allocation-free)
__device__ __half g_qkv[PT * PD3];              // fused fp16 Q|K|V
__device__ __half g_xh [PT * PD];               // fp16 x
__device__ __half g_wh [4 * (size_t)PD * PD];   // fp16 wq,wk,wv,wo (concat)
__device__ __half g_aoh[PT * PD];               // fp16 attention output
__device__ float  g_cos[PW * 64];               // rope tables
__device__ float  g_sin[PW * 64];

// ---------------------------------------------------------------------------
// PTX helpers
// ---------------------------------------------------------------------------
__device__ __forceinline__ void cp_async16(uint32_t saddr, const void* gptr) {
    asm volatile("cp.async.cg.shared.global [%0], [%1], 16;\n" :: "r"(saddr), "l"(gptr));
}
__device__ __forceinline__ void mma_f16(float* c, const uint32_t* a, const uint32_t* b) {
    asm volatile(
        "mma.sync.aligned.m16n8k16.row.col.f32.f16.f16.f32 "
        "{%0,%1,%2,%3}, {%4,%5,%6,%7}, {%8,%9}, {%0,%1,%2,%3};"
        : "+f"(c[0]), "+f"(c[1]), "+f"(c[2]), "+f"(c[3])
        : "r"(a[0]), "r"(a[1]), "r"(a[2]), "r"(a[3]), "r"(b[0]), "r"(b[1]));
}
__device__ __forceinline__ void ldsm_x4(uint32_t* r, uint32_t addr) {
    asm volatile("ldmatrix.sync.aligned.m8n8.x4.shared.b16 {%0,%1,%2,%3}, [%4];"
        : "=r"(r[0]), "=r"(r[1]), "=r"(r[2]), "=r"(r[3]) : "r"(addr));
}
__device__ __forceinline__ void ldsm_x4_t(uint32_t* r, uint32_t addr) {
    asm volatile("ldmatrix.sync.aligned.m8n8.x4.trans.shared.b16 {%0,%1,%2,%3}, [%4];"
        : "=r"(r[0]), "=r"(r[1]), "=r"(r[2]), "=r"(r[3]) : "r"(addr));
}

// ---------------------------------------------------------------------------
// fp16 tensor-core GEMM (R9 config — best measured; FROZEN): C = A * W^T.
// CTA 128x128, BK=64 halves, 256 threads = 8 warps (2m x 4n), warp tile 64x32.
// 3-stage circular cp.async pipeline, ldmatrix fragments, m16n8k16. 2 CTAs/SM.
// ---------------------------------------------------------------------------
#define BM 128
#define BN 128
#define BKH 64
#define KST 72                 // BKH + 8 pad (144B rows; ldmatrix conflict-free)
#define NST 3

template <typename OutT>
__global__ __launch_bounds__(256, 2)
void gemm_f16(const __half* __restrict__ A, const __half* __restrict__ W,
              OutT* __restrict__ C, int M, int N, int K)
{
    extern __shared__ __half smh[];
    __half* sA = smh;                        // [3][128][72]
    __half* sB = smh + NST * BM * KST;

    const int tid  = threadIdx.x;
    const int bm   = blockIdx.y * BM;
    const int bn   = blockIdx.x * BN;
    const int warp = tid >> 5;
    const int lane = tid & 31;
    const int wm   = (warp & 1) * 64;
    const int wn   = (warp >> 1) * 32;
    const int lr   = lane >> 2;
    const int lc   = lane & 3;

    float acc[4][4][4];
#pragma unroll
    for (int i = 0; i < 4; i++)
#pragma unroll
        for (int j = 0; j < 4; j++)
#pragma unroll
            for (int r = 0; r < 4; r++) acc[i][j][r] = 0.0f;

    const int T = K / BKH;                   // 32

    auto load_tile = [&](int t, int buf) {
        const int k0 = t * BKH;
        __half* a_dst = sA + buf * BM * KST;
        __half* b_dst = sB + buf * BM * KST;
#pragma unroll
        for (int i = 0; i < 8; i++) {
            int c   = tid + i * 256;
            int isB = c >> 10;
            int idx = c & 1023;
            int r   = idx >> 3;
            int c8  = (idx & 7) * 8;
            const __half* g = isB ? &W[(size_t)(bn + r) * K + k0 + c8]
                                  : &A[(size_t)(bm + r) * K + k0 + c8];
            __half* d = (isB ? b_dst : a_dst) + r * KST + c8;
            cp_async16((uint32_t)__cvta_generic_to_shared(d), g);
        }
        asm volatile("cp.async.commit_group;\n");
    };

    load_tile(0, 0);
    load_tile(1, 1);

    const int a_r = (lane & 15);
    const int a_c = (lane >> 4) * 8;
    const int b_r = (lane & 7) + (lane >> 4) * 8;
    const int b_c = ((lane >> 3) & 1) * 8;

    int buf = 0;
    for (int t = 0; t < T; t++) {
        if (t < T - 1) { asm volatile("cp.async.wait_group 1;\n"); }
        else           { asm volatile("cp.async.wait_group 0;\n"); }
        __syncthreads();

        if (t + 2 < T) {
            int nb = buf + 2; if (nb >= NST) nb -= NST;
            load_tile(t + 2, nb);
        }

        const __half* a_s = sA + buf * BM * KST;
        const __half* b_s = sB + buf * BM * KST;

#pragma unroll
        for (int kk = 0; kk < 4; kk++) {
            const int kb = kk * 16;
            uint32_t af[4][4];
#pragma unroll
            for (int mt = 0; mt < 4; mt++) {
                uint32_t ad = (uint32_t)__cvta_generic_to_shared(
                    a_s + (wm + mt * 16 + a_r) * KST + kb + a_c);
                ldsm_x4(af[mt], ad);
            }
            uint32_t bf[2][4];
#pragma unroll
            for (int p = 0; p < 2; p++) {
                uint32_t bd = (uint32_t)__cvta_generic_to_shared(
                    b_s + (wn + p * 16 + b_r) * KST + kb + b_c);
                ldsm_x4(bf[p], bd);
            }
#pragma unroll
            for (int mt = 0; mt < 4; mt++)
#pragma unroll
                for (int nt = 0; nt < 4; nt++)
                    mma_f16(acc[mt][nt], af[mt], &bf[nt >> 1][(nt & 1) * 2]);
        }
        buf++; if (buf == NST) buf = 0;
    }

#pragma unroll
    for (int mt = 0; mt < 4; mt++) {
#pragma unroll
        for (int nt = 0; nt < 4; nt++) {
            int r0 = bm + wm + mt * 16 + lr;
            int cc = bn + wn + nt * 8 + 2 * lc;
            if (sizeof(OutT) == 4) {
                float* Cf = (float*)C;
                *(float2*)&Cf[(size_t)(r0    ) * N + cc] = make_float2(acc[mt][nt][0], acc[mt][nt][1]);
                *(float2*)&Cf[(size_t)(r0 + 8) * N + cc] = make_float2(acc[mt][nt][2], acc[mt][nt][3]);
            } else {
                __half* Ch = (__half*)C;
                __half2 h0 = __floats2half2_rn(acc[mt][nt][0], acc[mt][nt][1]);
                __half2 h1 = __floats2half2_rn(acc[mt][nt][2], acc[mt][nt][3]);
                *(uint32_t*)&Ch[(size_t)(r0    ) * N + cc] = *(uint32_t*)&h0;
                *(uint32_t*)&Ch[(size_t)(r0 + 8) * N + cc] = *(uint32_t*)&h1;
            }
        }
    }
}

// ---------------------------------------------------------------------------
// Fused prep with MLP=2: thread i converts x-chunk i AND weight-chunk i.
// ---------------------------------------------------------------------------
#define N4X (PT * PD / 4)          // 4,194,304
#define N4W (PD * PD / 4)          // 1,048,576

__global__ void prep_kernel(const float4* __restrict__ x,
                            const float4* __restrict__ w0, const float4* __restrict__ w1,
                            const float4* __restrict__ w2, const float4* __restrict__ w3,
                            __half* __restrict__ xh, __half* __restrict__ wh)
{
    int i = blockIdx.x * blockDim.x + threadIdx.x;
    if (i >= N4X) return;
    int sel = i >> 20;                        // i / N4W  (4*N4W == N4X)
    int rem = i & (N4W - 1);
    const float4* s = (sel == 0) ? w0 : (sel == 1) ? w1 : (sel == 2) ? w2 : w3;
    float4 v1 = x[i];
    float4 v2 = s[rem];

    __half2 a0 = __floats2half2_rn(v1.x, v1.y);
    __half2 a1 = __floats2half2_rn(v1.z, v1.w);
    uint2 o1; o1.x = *(uint32_t*)&a0; o1.y = *(uint32_t*)&a1;
    *(uint2*)&xh[(size_t)i * 4] = o1;

    __half2 b0 = __floats2half2_rn(v2.x, v2.y);
    __half2 b1 = __floats2half2_rn(v2.z, v2.w);
    uint2 o2; o2.x = *(uint32_t*)&b0; o2.y = *(uint32_t*)&b1;
    *(uint2*)&wh[(size_t)i * 4] = o2;
}

// ---------------------------------------------------------------------------
// RoPE cos/sin tables
// ---------------------------------------------------------------------------
__global__ void rope_table_kernel(float* __restrict__ ct, float* __restrict__ st)
{
    int t = blockIdx.x * blockDim.x + threadIdx.x;
    if (t >= PW * 64) return;
    int w = t >> 6;
    int j = t & 63;
    const float c_ln = 9.210340371976184f / 64.0f;
    float freq = (float)w * expf(-(float)j * c_ln);
    ct[t] = cosf(freq);
    st[t] = sinf(freq);
}

// ---------------------------------------------------------------------------
// Tensor-core block-local attention: fused RoPE, fp16 QKV input, direct mask
// loads. PV phase split into two 64-col halves to shrink register pressure
// (oacc 32 regs) -> fits 128-reg cap -> 2 CTAs/SM. 8 warps, 16 q-rows/warp.
// ---------------------------------------------------------------------------
#define AST 136                 // QKV smem row stride in halves (272B)

__global__ __launch_bounds__(256, 2)
void attn_mma(const __half* __restrict__ QKV, const float* __restrict__ mask,
              const float* __restrict__ ctab, const float* __restrict__ stab,
              __half* __restrict__ O)
{
    extern __shared__ __half sh[];
    __half* sQ = sh;                   // [128][136]
    __half* sK = sh + 128 * AST;
    __half* sV = sh + 2 * 128 * AST;

    const int c = blockIdx.x;
    const int h = blockIdx.y;
    const int b = blockIdx.z;
    const int tid  = threadIdx.x;
    const int warp = tid >> 5;
    const int lane = tid & 31;
    const int lr   = lane >> 2;
    const int lc   = lane & 3;
    const int m0   = warp * 16;

    const int tb    = b * PS + c * PW;
    const int cbase = h * PHD;

    // ---- Load Q,K with fused RoPE (fp16 source; pairs d and d+64) ----
#pragma unroll
    for (int l = 0; l < 8; l++) {
        int f  = tid + l * 256;            // 0..2047 = 128 rows x 16 chunks
        int r  = f >> 4;
        int d4 = (f & 15) << 2;            // 0..60
        size_t g0 = (size_t)(tb + r) * PD3 + cbase + d4;
        uint2 uqa = *(const uint2*)&QKV[g0];
        uint2 uqb = *(const uint2*)&QKV[g0 + 64];
        uint2 uka = *(const uint2*)&QKV[g0 + PD];
        uint2 ukb = *(const uint2*)&QKV[g0 + PD + 64];
        float2 qa01 = __half22float2(*(__half2*)&uqa.x);
        float2 qa23 = __half22float2(*(__half2*)&uqa.y);
        float2 qb01 = __half22float2(*(__half2*)&uqb.x);
        float2 qb23 = __half22float2(*(__half2*)&uqb.y);
        float2 ka01 = __half22float2(*(__half2*)&uka.x);
        float2 ka23 = __half22float2(*(__half2*)&uka.y);
        float2 kb01 = __half22float2(*(__half2*)&ukb.x);
        float2 kb23 = __half22float2(*(__half2*)&ukb.y);
        float4 cv = *(const float4*)&ctab[r * 64 + d4];
        float4 sv = *(const float4*)&stab[r * 64 + d4];

        __half2 h0, h1;
        uint2 u;
        h0 = __floats2half2_rn(qa01.x * cv.x - qb01.x * sv.x,
                               qa01.y * cv.y - qb01.y * sv.y);
        h1 = __floats2half2_rn(qa23.x * cv.z - qb23.x * sv.z,
                               qa23.y * cv.w - qb23.y * sv.w);
        u.x = *(uint32_t*)&h0; u.y = *(uint32_t*)&h1;
        *(uint2*)&sQ[r * AST + d4] = u;
        h0 = __floats2half2_rn(qb01.x * cv.x + qa01.x * sv.x,
                               qb01.y * cv.y + qa01.y * sv.y);
        h1 = __floats2half2_rn(qb23.x * cv.z + qa23.x * sv.z,
                               qb23.y * cv.w + qa23.y * sv.w);
        u.x = *(uint32_t*)&h0; u.y = *(uint32_t*)&h1;
        *(uint2*)&sQ[r * AST + d4 + 64] = u;
        h0 = __floats2half2_rn(ka01.x * cv.x - kb01.x * sv.x,
                               ka01.y * cv.y - kb01.y * sv.y);
        h1 = __floats2half2_rn(ka23.x * cv.z - kb23.x * sv.z,
                               ka23.y * cv.w - kb23.y * sv.w);
        u.x = *(uint32_t*)&h0; u.y = *(uint32_t*)&h1;
        *(uint2*)&sK[r * AST + d4] = u;
        h0 = __floats2half2_rn(kb01.x * cv.x + ka01.x * sv.x,
                               kb01.y * cv.y + ka01.y * sv.y);
        h1 = __floats2half2_rn(kb23.x * cv.z + ka23.x * sv.z,
                               kb23.y * cv.w + ka23.y * sv.w);
        u.x = *(uint32_t*)&h0; u.y = *(uint32_t*)&h1;
        *(uint2*)&sK[r * AST + d4 + 64] = u;
    }
    // ---- Load V (fp16, straight copy) ----
#pragma unroll
    for (int l = 0; l < 8; l++) {
        int f  = tid + l * 256;
        int r  = f >> 4;
        int d4 = (f & 15) << 3;            // 8-half chunks
        uint4 uv = *(const uint4*)&QKV[(size_t)(tb + r) * PD3 + cbase + 2 * PD + d4];
        *(uint4*)&sV[r * AST + d4] = uv;
    }
    __syncthreads();

    // ---- Phase 1: S = Q K^T ----
    float sacc[16][4];
#pragma unroll
    for (int i = 0; i < 16; i++)
#pragma unroll
        for (int j = 0; j < 4; j++) sacc[i][j] = 0.0f;

    const int a_r = m0 + (lane & 15);
    const int a_c = (lane >> 4) * 8;
    const int b_r = (lane & 7) + (lane >> 4) * 8;
    const int b_c = ((lane >> 3) & 1) * 8;

#pragma unroll
    for (int ks = 0; ks < 8; ks++) {
        const int kb = ks * 16;
        uint32_t af[4];
        ldsm_x4(af, (uint32_t)__cvta_generic_to_shared(sQ + a_r * AST + kb + a_c));
#pragma unroll
        for (int p = 0; p < 8; p++) {
            uint32_t bf[4];
            ldsm_x4(bf, (uint32_t)__cvta_generic_to_shared(
                        sK + (p * 16 + b_r) * AST + kb + b_c));
            mma_f16(sacc[2 * p    ], af, bf);
            mma_f16(sacc[2 * p + 1], af, bf + 2);
        }
    }

    // ---- mask + clamp (direct global loads) ----
    const float scale = 0.08838834764831845f;
    const float NEG = -3.402823466e38f;
    const float* mrow0 = mask + (size_t)b * PS * PS
                       + (size_t)(c * PW + m0 + lr) * PS + c * PW;
    const float* mrow1 = mrow0 + 8 * PS;
#pragma unroll
    for (int nt = 0; nt < 16; nt++) {
        float2 mv0 = *(const float2*)&mrow0[nt * 8 + 2 * lc];
        float2 mv1 = *(const float2*)&mrow1[nt * 8 + 2 * lc];
        sacc[nt][0] = fmaxf(fmaf(sacc[nt][0], scale, mv0.x), NEG);
        sacc[nt][1] = fmaxf(fmaf(sacc[nt][1], scale, mv0.y), NEG);
        sacc[nt][2] = fmaxf(fmaf(sacc[nt][2], scale, mv1.x), NEG);
        sacc[nt][3] = fmaxf(fmaf(sacc[nt][3], scale, mv1.y), NEG);
    }

    // ---- softmax ----
    float mx0 = -FLT_MAX, mx1 = -FLT_MAX;
#pragma unroll
    for (int nt = 0; nt < 16; nt++) {
        mx0 = fmaxf(mx0, fmaxf(sacc[nt][0], sacc[nt][1]));
        mx1 = fmaxf(mx1, fmaxf(sacc[nt][2], sacc[nt][3]));
    }
    mx0 = fmaxf(mx0, __shfl_xor_sync(0xFFFFFFFF, mx0, 1));
    mx0 = fmaxf(mx0, __shfl_xor_sync(0xFFFFFFFF, mx0, 2));
    mx1 = fmaxf(mx1, __shfl_xor_sync(0xFFFFFFFF, mx1, 1));
    mx1 = fmaxf(mx1, __shfl_xor_sync(0xFFFFFFFF, mx1, 2));

    float sum0 = 0.f, sum1 = 0.f;
#pragma unroll
    for (int nt = 0; nt < 16; nt++) {
        sacc[nt][0] = __expf(sacc[nt][0] - mx0);
        sacc[nt][1] = __expf(sacc[nt][1] - mx0);
        sacc[nt][2] = __expf(sacc[nt][2] - mx1);
        sacc[nt][3] = __expf(sacc[nt][3] - mx1);
        sum0 += sacc[nt][0] + sacc[nt][1];
        sum1 += sacc[nt][2] + sacc[nt][3];
    }
    sum0 += __shfl_xor_sync(0xFFFFFFFF, sum0, 1);
    sum0 += __shfl_xor_sync(0xFFFFFFFF, sum0, 2);
    sum1 += __shfl_xor_sync(0xFFFFFFFF, sum1, 1);
    sum1 += __shfl_xor_sync(0xFFFFFFFF, sum1, 2);
    const float inv0 = 1.0f / sum0;
    const float inv1 = 1.0f / sum1;

    // P fragments (fp16), sacc dies here
    uint32_t pf[8][4];
#pragma unroll
    for (int ks = 0; ks < 8; ks++) {
        __half2 p0 = __floats2half2_rn(sacc[2 * ks][0] * inv0, sacc[2 * ks][1] * inv0);
        __half2 p1 = __floats2half2_rn(sacc[2 * ks][2] * inv1, sacc[2 * ks][3] * inv1);
        __half2 p2 = __floats2half2_rn(sacc[2 * ks + 1][0] * inv0, sacc[2 * ks + 1][1] * inv0);
        __half2 p3 = __floats2half2_rn(sacc[2 * ks + 1][2] * inv1, sacc[2 * ks + 1][3] * inv1);
        pf[ks][0] = *(uint32_t*)&p0;
        pf[ks][1] = *(uint32_t*)&p1;
        pf[ks][2] = *(uint32_t*)&p2;
        pf[ks][3] = *(uint32_t*)&p3;
    }

    // ---- Phase 2: O = P V, split into two 64-col halves (oacc 32 regs) ----
    const int v_r = (lane & 15);
    const int v_c = (lane >> 4) * 8;
#pragma unroll
    for (int dh = 0; dh < 2; dh++) {
        float oacc[8][4];
#pragma unroll
        for (int i = 0; i < 8; i++)
#pragma unroll
            for (int j = 0; j < 4; j++) oacc[i][j] = 0.0f;

#pragma unroll
        for (int ks = 0; ks < 8; ks++) {
            const int kb = ks * 16;
#pragma unroll
            for (int pl = 0; pl < 4; pl++) {
                const int p = dh * 4 + pl;
                uint32_t bf[4];
                ldsm_x4_t(bf, (uint32_t)__cvta_generic_to_shared(
                              sV + (kb + v_r) * AST + p * 16 + v_c));
                mma_f16(oacc[2 * pl    ], pf[ks], bf);
                mma_f16(oacc[2 * pl + 1], pf[ks], bf + 2);
            }
        }

#pragma unroll
        for (int nt = 0; nt < 8; nt++) {
            int col = cbase + dh * 64 + nt * 8 + 2 * lc;
            size_t g0 = (size_t)(tb + m0 + lr    ) * PD + col;
            size_t g1 = (size_t)(tb + m0 + lr + 8) * PD + col;
            __half2 o0 = __floats2half2_rn(oacc[nt][0], oacc[nt][1]);
            __half2 o1 = __floats2half2_rn(oacc[nt][2], oacc[nt][3]);
            *(uint32_t*)&O[g0] = *(uint32_t*)&o0;
            *(uint32_t*)&O[g1] = *(uint32_t*)&o1;
        }
    }
}

// ---------------------------------------------------------------------------
extern "C" void kernel_launch(void* const* d_in, const int* in_sizes, int n_in,
                              void* d_out, int out_size)
{
    const float* x    = (const float*)d_in[0];
    const float* mask = (const float*)d_in[1];
    const float* wq   = (const float*)d_in[2];
    const float* wk   = (const float*)d_in[3];
    const float* wv   = (const float*)d_in[4];
    const float* wo   = (const float*)d_in[5];
    float* out = (float*)d_out;

    void *pqkv, *pxh, *pwh, *paoh, *pct, *pst;
    cudaGetSymbolAddress(&pqkv, g_qkv);
    cudaGetSymbolAddress(&pxh,  g_xh);
    cudaGetSymbolAddress(&pwh,  g_wh);
    cudaGetSymbolAddress(&paoh, g_aoh);
    cudaGetSymbolAddress(&pct,  g_cos);
    cudaGetSymbolAddress(&pst,  g_sin);
    __half* qkv  = (__half*)pqkv;
    __half* xh   = (__half*)pxh;
    __half* wh   = (__half*)pwh;
    __half* aoh  = (__half*)paoh;
    float*  ctab = (float*)pct;
    float*  stab = (float*)pst;

    // Fused prep (MLP=2) + rope tables
    prep_kernel<<<N4X / 256, 256>>>((const float4*)x,
                                    (const float4*)wq, (const float4*)wk,
                                    (const float4*)wv, (const float4*)wo,
                                    xh, wh);
    rope_table_kernel<<<(PW * 64) / 256, 256>>>(ctab, stab);

    size_t gsmem = (size_t)2 * NST * BM * KST * sizeof(__half);   // 110,592 B
    cudaFuncSetAttribute(gemm_f16<__half>, cudaFuncAttributeMaxDynamicSharedMemorySize,
                         (int)gsmem);
    cudaFuncSetAttribute(gemm_f16<float>, cudaFuncAttributeMaxDynamicSharedMemorySize,
                         (int)gsmem);

    // Fused QKV projection: [8192 x 2048] x [6144 x 2048]^T -> fp16 [8192 x 6144]
    dim3 gqkv(PD3 / BN, PT / BM);            // 48 x 64
    gemm_f16<__half><<<gqkv, 256, gsmem>>>(xh, wh, qkv, PT, PD3, PD);

    // Attention (rope fused; 2 CTAs/SM target)
    size_t asmem = (size_t)3 * 128 * AST * sizeof(__half);  // 104,448 B
    cudaFuncSetAttribute(attn_mma, cudaFuncAttributeMaxDynamicSharedMemorySize,
                         (int)asmem);
    attn_mma<<<dim3(PNC, PH, PB), 256, asmem>>>(qkv, mask, ctab, stab, aoh);

    // Output projection (fp32 out)
    dim3 gout(PD / BN, PT / BM);             // 16 x 64
    gemm_f16<float><<<gout, 256, gsmem>>>(aoh, wh + 3 * (size_t)PD * PD, out, PT, PD, PD);
}

// round 16
// speedup vs baseline: 1.2714x; 1.1425x over previous
#include <cuda_runtime.h>
#include <cuda_fp16.h>
#include <math.h>
#include <float.h>
#include <stdint.h>

// Problem constants
#define PB 2
#define PS 4096
#define PD 2048
#define PD3 6144              // fused QKV output width
#define PH 16
#define PHD 128
#define PW 128
#define PNC 32
#define PT (PB*PS)            // 8192 tokens

// Scratch (allocation-free)
__device__ __half g_qkv[PT * PD3];              // fused fp16 Q|K|V
__device__ __half g_xh [PT * PD];               // fp16 x
__device__ __half g_wh [4 * (size_t)PD * PD];   // fp16 wq,wk,wv,wo (concat)
__device__ __half g_aoh[PT * PD];               // fp16 attention output
__device__ float  g_cos[PW * 64];               // rope tables
__device__ float  g_sin[PW * 64];

// ---------------------------------------------------------------------------
// PTX helpers
// ---------------------------------------------------------------------------
__device__ __forceinline__ void cp_async16(uint32_t saddr, const void* gptr) {
    asm volatile("cp.async.cg.shared.global [%0], [%1], 16;\n" :: "r"(saddr), "l"(gptr));
}
__device__ __forceinline__ void mma_f16(float* c, const uint32_t* a, const uint32_t* b) {
    asm volatile(
        "mma.sync.aligned.m16n8k16.row.col.f32.f16.f16.f32 "
        "{%0,%1,%2,%3}, {%4,%5,%6,%7}, {%8,%9}, {%0,%1,%2,%3};"
        : "+f"(c[0]), "+f"(c[1]), "+f"(c[2]), "+f"(c[3])
        : "r"(a[0]), "r"(a[1]), "r"(a[2]), "r"(a[3]), "r"(b[0]), "r"(b[1]));
}
__device__ __forceinline__ void ldsm_x4(uint32_t* r, uint32_t addr) {
    asm volatile("ldmatrix.sync.aligned.m8n8.x4.shared.b16 {%0,%1,%2,%3}, [%4];"
        : "=r"(r[0]), "=r"(r[1]), "=r"(r[2]), "=r"(r[3]) : "r"(addr));
}
__device__ __forceinline__ void ldsm_x4_t(uint32_t* r, uint32_t addr) {
    asm volatile("ldmatrix.sync.aligned.m8n8.x4.trans.shared.b16 {%0,%1,%2,%3}, [%4];"
        : "=r"(r[0]), "=r"(r[1]), "=r"(r[2]), "=r"(r[3]) : "r"(addr));
}

// ---------------------------------------------------------------------------
// fp16 tensor-core GEMM (R9 tile config — frozen): C = A * W^T, fp32 acc.
// CTA 128x128, BK=64 halves, 256 threads = 8 warps (2m x 4n), warp tile 64x32.
// 3-stage circular cp.async pipeline; the next-stage prefetch is INTERLEAVED
// through the kk-loop (2 chunks per kk) to keep the tensor queue fed while
// the LSU issues the LDGSTS train. ldmatrix fragments, m16n8k16. 2 CTAs/SM.
// ---------------------------------------------------------------------------
#define BM 128
#define BN 128
#define BKH 64
#define KST 72                 // BKH + 8 pad (144B rows; ldmatrix conflict-free)
#define NST 3

template <typename OutT>
__global__ __launch_bounds__(256, 2)
void gemm_f16(const __half* __restrict__ A, const __half* __restrict__ W,
              OutT* __restrict__ C, int M, int N, int K)
{
    extern __shared__ __half smh[];
    __half* sA = smh;                        // [3][128][72]
    __half* sB = smh + NST * BM * KST;

    const int tid  = threadIdx.x;
    const int bm   = blockIdx.y * BM;
    const int bn   = blockIdx.x * BN;
    const int warp = tid >> 5;
    const int lane = tid & 31;
    const int wm   = (warp & 1) * 64;
    const int wn   = (warp >> 1) * 32;
    const int lr   = lane >> 2;
    const int lc   = lane & 3;

    float acc[4][4][4];
#pragma unroll
    for (int i = 0; i < 4; i++)
#pragma unroll
        for (int j = 0; j < 4; j++)
#pragma unroll
            for (int r = 0; r < 4; r++) acc[i][j][r] = 0.0f;

    const int T = K / BKH;                   // 32

    // full-stage loader (prologue only)
    auto load_tile = [&](int t, int buf) {
        const int k0 = t * BKH;
        __half* a_dst = sA + buf * BM * KST;
        __half* b_dst = sB + buf * BM * KST;
#pragma unroll
        for (int i = 0; i < 8; i++) {
            int c   = tid + i * 256;
            int isB = c >> 10;
            int idx = c & 1023;
            int r   = idx >> 3;
            int c8  = (idx & 7) * 8;
            const __half* g = isB ? &W[(size_t)(bn + r) * K + k0 + c8]
                                  : &A[(size_t)(bm + r) * K + k0 + c8];
            __half* d = (isB ? b_dst : a_dst) + r * KST + c8;
            cp_async16((uint32_t)__cvta_generic_to_shared(d), g);
        }
        asm volatile("cp.async.commit_group;\n");
    };

    // partial loader: 2 of the 8 chunks (pair = 0..3)
    auto load_part = [&](int t, int buf, int pair) {
        const int k0 = t * BKH;
        __half* a_dst = sA + buf * BM * KST;
        __half* b_dst = sB + buf * BM * KST;
#pragma unroll
        for (int i = pair * 2; i < pair * 2 + 2; i++) {
            int c   = tid + i * 256;
            int isB = c >> 10;
            int idx = c & 1023;
            int r   = idx >> 3;
            int c8  = (idx & 7) * 8;
            const __half* g = isB ? &W[(size_t)(bn + r) * K + k0 + c8]
                                  : &A[(size_t)(bm + r) * K + k0 + c8];
            __half* d = (isB ? b_dst : a_dst) + r * KST + c8;
            cp_async16((uint32_t)__cvta_generic_to_shared(d), g);
        }
    };

    load_tile(0, 0);
    load_tile(1, 1);

    const int a_r = (lane & 15);
    const int a_c = (lane >> 4) * 8;
    const int b_r = (lane & 7) + (lane >> 4) * 8;
    const int b_c = ((lane >> 3) & 1) * 8;

    int buf = 0;
    for (int t = 0; t < T; t++) {
        if (t < T - 1) { asm volatile("cp.async.wait_group 1;\n"); }
        else           { asm volatile("cp.async.wait_group 0;\n"); }
        __syncthreads();

        const bool pf = (t + 2 < T);
        int nb = buf + 2; if (nb >= NST) nb -= NST;

        const __half* a_s = sA + buf * BM * KST;
        const __half* b_s = sB + buf * BM * KST;

#pragma unroll
        for (int kk = 0; kk < 4; kk++) {
            // interleaved prefetch: 2 chunks of stage t+2 per kk
            if (pf) load_part(t + 2, nb, kk);

            const int kb = kk * 16;
            uint32_t af[4][4];
#pragma unroll
            for (int mt = 0; mt < 4; mt++) {
                uint32_t ad = (uint32_t)__cvta_generic_to_shared(
                    a_s + (wm + mt * 16 + a_r) * KST + kb + a_c);
                ldsm_x4(af[mt], ad);
            }
            uint32_t bf[2][4];
#pragma unroll
            for (int p = 0; p < 2; p++) {
                uint32_t bd = (uint32_t)__cvta_generic_to_shared(
                    b_s + (wn + p * 16 + b_r) * KST + kb + b_c);
                ldsm_x4(bf[p], bd);
            }
#pragma unroll
            for (int mt = 0; mt < 4; mt++)
#pragma unroll
                for (int nt = 0; nt < 4; nt++)
                    mma_f16(acc[mt][nt], af[mt], &bf[nt >> 1][(nt & 1) * 2]);
        }
        if (pf) { asm volatile("cp.async.commit_group;\n"); }

        buf++; if (buf == NST) buf = 0;
    }

#pragma unroll
    for (int mt = 0; mt < 4; mt++) {
#pragma unroll
        for (int nt = 0; nt < 4; nt++) {
            int r0 = bm + wm + mt * 16 + lr;
            int cc = bn + wn + nt * 8 + 2 * lc;
            if (sizeof(OutT) == 4) {
                float* Cf = (float*)C;
                *(float2*)&Cf[(size_t)(r0    ) * N + cc] = make_float2(acc[mt][nt][0], acc[mt][nt][1]);
                *(float2*)&Cf[(size_t)(r0 + 8) * N + cc] = make_float2(acc[mt][nt][2], acc[mt][nt][3]);
            } else {
                __half* Ch = (__half*)C;
                __half2 h0 = __floats2half2_rn(acc[mt][nt][0], acc[mt][nt][1]);
                __half2 h1 = __floats2half2_rn(acc[mt][nt][2], acc[mt][nt][3]);
                *(uint32_t*)&Ch[(size_t)(r0    ) * N + cc] = *(uint32_t*)&h0;
                *(uint32_t*)&Ch[(size_t)(r0 + 8) * N + cc] = *(uint32_t*)&h1;
            }
        }
    }
}

// ---------------------------------------------------------------------------
// Fused prep with MLP=2: thread i converts x-chunk i AND weight-chunk i.
// ---------------------------------------------------------------------------
#define N4X (PT * PD / 4)          // 4,194,304
#define N4W (PD * PD / 4)          // 1,048,576

__global__ void prep_kernel(const float4* __restrict__ x,
                            const float4* __restrict__ w0, const float4* __restrict__ w1,
                            const float4* __restrict__ w2, const float4* __restrict__ w3,
                            __half* __restrict__ xh, __half* __restrict__ wh)
{
    int i = blockIdx.x * blockDim.x + threadIdx.x;
    if (i >= N4X) return;
    int sel = i >> 20;                        // i / N4W  (4*N4W == N4X)
    int rem = i & (N4W - 1);
    const float4* s = (sel == 0) ? w0 : (sel == 1) ? w1 : (sel == 2) ? w2 : w3;
    float4 v1 = x[i];
    float4 v2 = s[rem];

    __half2 a0 = __floats2half2_rn(v1.x, v1.y);
    __half2 a1 = __floats2half2_rn(v1.z, v1.w);
    uint2 o1; o1.x = *(uint32_t*)&a0; o1.y = *(uint32_t*)&a1;
    *(uint2*)&xh[(size_t)i * 4] = o1;

    __half2 b0 = __floats2half2_rn(v2.x, v2.y);
    __half2 b1 = __floats2half2_rn(v2.z, v2.w);
    uint2 o2; o2.x = *(uint32_t*)&b0; o2.y = *(uint32_t*)&b1;
    *(uint2*)&wh[(size_t)i * 4] = o2;
}

// ---------------------------------------------------------------------------
// RoPE cos/sin tables
// ---------------------------------------------------------------------------
__global__ void rope_table_kernel(float* __restrict__ ct, float* __restrict__ st)
{
    int t = blockIdx.x * blockDim.x + threadIdx.x;
    if (t >= PW * 64) return;
    int w = t >> 6;
    int j = t & 63;
    const float c_ln = 9.210340371976184f / 64.0f;
    float freq = (float)w * expf(-(float)j * c_ln);
    ct[t] = cosf(freq);
    st[t] = sinf(freq);
}

// ---------------------------------------------------------------------------
// Tensor-core block-local attention (R14 config): fused RoPE, fp16 QKV input,
// direct mask loads, PV split into two 64-col halves, 2 CTAs/SM.
// ---------------------------------------------------------------------------
#define AST 136                 // QKV smem row stride in halves (272B)

__global__ __launch_bounds__(256, 2)
void attn_mma(const __half* __restrict__ QKV, const float* __restrict__ mask,
              const float* __restrict__ ctab, const float* __restrict__ stab,
              __half* __restrict__ O)
{
    extern __shared__ __half sh[];
    __half* sQ = sh;                   // [128][136]
    __half* sK = sh + 128 * AST;
    __half* sV = sh + 2 * 128 * AST;

    const int c = blockIdx.x;
    const int h = blockIdx.y;
    const int b = blockIdx.z;
    const int tid  = threadIdx.x;
    const int warp = tid >> 5;
    const int lane = tid & 31;
    const int lr   = lane >> 2;
    const int lc   = lane & 3;
    const int m0   = warp * 16;

    const int tb    = b * PS + c * PW;
    const int cbase = h * PHD;

    // ---- Load Q,K with fused RoPE (fp16 source; pairs d and d+64) ----
#pragma unroll
    for (int l = 0; l < 8; l++) {
        int f  = tid + l * 256;            // 0..2047 = 128 rows x 16 chunks
        int r  = f >> 4;
        int d4 = (f & 15) << 2;            // 0..60
        size_t g0 = (size_t)(tb + r) * PD3 + cbase + d4;
        uint2 uqa = *(const uint2*)&QKV[g0];
        uint2 uqb = *(const uint2*)&QKV[g0 + 64];
        uint2 uka = *(const uint2*)&QKV[g0 + PD];
        uint2 ukb = *(const uint2*)&QKV[g0 + PD + 64];
        float2 qa01 = __half22float2(*(__half2*)&uqa.x);
        float2 qa23 = __half22float2(*(__half2*)&uqa.y);
        float2 qb01 = __half22float2(*(__half2*)&uqb.x);
        float2 qb23 = __half22float2(*(__half2*)&uqb.y);
        float2 ka01 = __half22float2(*(__half2*)&uka.x);
        float2 ka23 = __half22float2(*(__half2*)&uka.y);
        float2 kb01 = __half22float2(*(__half2*)&ukb.x);
        float2 kb23 = __half22float2(*(__half2*)&ukb.y);
        float4 cv = *(const float4*)&ctab[r * 64 + d4];
        float4 sv = *(const float4*)&stab[r * 64 + d4];

        __half2 h0, h1;
        uint2 u;
        h0 = __floats2half2_rn(qa01.x * cv.x - qb01.x * sv.x,
                               qa01.y * cv.y - qb01.y * sv.y);
        h1 = __floats2half2_rn(qa23.x * cv.z - qb23.x * sv.z,
                               qa23.y * cv.w - qb23.y * sv.w);
        u.x = *(uint32_t*)&h0; u.y = *(uint32_t*)&h1;
        *(uint2*)&sQ[r * AST + d4] = u;
        h0 = __floats2half2_rn(qb01.x * cv.x + qa01.x * sv.x,
                               qb01.y * cv.y + qa01.y * sv.y);
        h1 = __floats2half2_rn(qb23.x * cv.z + qa23.x * sv.z,
                               qb23.y * cv.w + qa23.y * sv.w);
        u.x = *(uint32_t*)&h0; u.y = *(uint32_t*)&h1;
        *(uint2*)&sQ[r * AST + d4 + 64] = u;
        h0 = __floats2half2_rn(ka01.x * cv.x - kb01.x * sv.x,
                               ka01.y * cv.y - kb01.y * sv.y);
        h1 = __floats2half2_rn(ka23.x * cv.z - kb23.x * sv.z,
                               ka23.y * cv.w - kb23.y * sv.w);
        u.x = *(uint32_t*)&h0; u.y = *(uint32_t*)&h1;
        *(uint2*)&sK[r * AST + d4] = u;
        h0 = __floats2half2_rn(kb01.x * cv.x + ka01.x * sv.x,
                               kb01.y * cv.y + ka01.y * sv.y);
        h1 = __floats2half2_rn(kb23.x * cv.z + ka23.x * sv.z,
                               kb23.y * cv.w + ka23.y * sv.w);
        u.x = *(uint32_t*)&h0; u.y = *(uint32_t*)&h1;
        *(uint2*)&sK[r * AST + d4 + 64] = u;
    }
    // ---- Load V (fp16, straight copy) ----
#pragma unroll
    for (int l = 0; l < 8; l++) {
        int f  = tid + l * 256;
        int r  = f >> 4;
        int d4 = (f & 15) << 3;            // 8-half chunks
        uint4 uv = *(const uint4*)&QKV[(size_t)(tb + r) * PD3 + cbase + 2 * PD + d4];
        *(uint4*)&sV[r * AST + d4] = uv;
    }
    __syncthreads();

    // ---- Phase 1: S = Q K^T ----
    float sacc[16][4];
#pragma unroll
    for (int i = 0; i < 16; i++)
#pragma unroll
        for (int j = 0; j < 4; j++) sacc[i][j] = 0.0f;

    const int a_r = m0 + (lane & 15);
    const int a_c = (lane >> 4) * 8;
    const int b_r = (lane & 7) + (lane >> 4) * 8;
    const int b_c = ((lane >> 3) & 1) * 8;

#pragma unroll
    for (int ks = 0; ks < 8; ks++) {
        const int kb = ks * 16;
        uint32_t af[4];
        ldsm_x4(af, (uint32_t)__cvta_generic_to_shared(sQ + a_r * AST + kb + a_c));
#pragma unroll
        for (int p = 0; p < 8; p++) {
            uint32_t bf[4];
            ldsm_x4(bf, (uint32_t)__cvta_generic_to_shared(
                        sK + (p * 16 + b_r) * AST + kb + b_c));
            mma_f16(sacc[2 * p    ], af, bf);
            mma_f16(sacc[2 * p + 1], af, bf + 2);
        }
    }

    // ---- mask + clamp (direct global loads) ----
    const float scale = 0.08838834764831845f;
    const float NEG = -3.402823466e38f;
    const float* mrow0 = mask + (size_t)b * PS * PS
                       + (size_t)(c * PW + m0 + lr) * PS + c * PW;
    const float* mrow1 = mrow0 + 8 * PS;
#pragma unroll
    for (int nt = 0; nt < 16; nt++) {
        float2 mv0 = *(const float2*)&mrow0[nt * 8 + 2 * lc];
        float2 mv1 = *(const float2*)&mrow1[nt * 8 + 2 * lc];
        sacc[nt][0] = fmaxf(fmaf(sacc[nt][0], scale, mv0.x), NEG);
        sacc[nt][1] = fmaxf(fmaf(sacc[nt][1], scale, mv0.y), NEG);
        sacc[nt][2] = fmaxf(fmaf(sacc[nt][2], scale, mv1.x), NEG);
        sacc[nt][3] = fmaxf(fmaf(sacc[nt][3], scale, mv1.y), NEG);
    }

    // ---- softmax ----
    float mx0 = -FLT_MAX, mx1 = -FLT_MAX;
#pragma unroll
    for (int nt = 0; nt < 16; nt++) {
        mx0 = fmaxf(mx0, fmaxf(sacc[nt][0], sacc[nt][1]));
        mx1 = fmaxf(mx1, fmaxf(sacc[nt][2], sacc[nt][3]));
    }
    mx0 = fmaxf(mx0, __shfl_xor_sync(0xFFFFFFFF, mx0, 1));
    mx0 = fmaxf(mx0, __shfl_xor_sync(0xFFFFFFFF, mx0, 2));
    mx1 = fmaxf(mx1, __shfl_xor_sync(0xFFFFFFFF, mx1, 1));
    mx1 = fmaxf(mx1, __shfl_xor_sync(0xFFFFFFFF, mx1, 2));

    float sum0 = 0.f, sum1 = 0.f;
#pragma unroll
    for (int nt = 0; nt < 16; nt++) {
        sacc[nt][0] = __expf(sacc[nt][0] - mx0);
        sacc[nt][1] = __expf(sacc[nt][1] - mx0);
        sacc[nt][2] = __expf(sacc[nt][2] - mx1);
        sacc[nt][3] = __expf(sacc[nt][3] - mx1);
        sum0 += sacc[nt][0] + sacc[nt][1];
        sum1 += sacc[nt][2] + sacc[nt][3];
    }
    sum0 += __shfl_xor_sync(0xFFFFFFFF, sum0, 1);
    sum0 += __shfl_xor_sync(0xFFFFFFFF, sum0, 2);
    sum1 += __shfl_xor_sync(0xFFFFFFFF, sum1, 1);
    sum1 += __shfl_xor_sync(0xFFFFFFFF, sum1, 2);
    const float inv0 = 1.0f / sum0;
    const float inv1 = 1.0f / sum1;

    // P fragments (fp16), sacc dies here
    uint32_t pf[8][4];
#pragma unroll
    for (int ks = 0; ks < 8; ks++) {
        __half2 p0 = __floats2half2_rn(sacc[2 * ks][0] * inv0, sacc[2 * ks][1] * inv0);
        __half2 p1 = __floats2half2_rn(sacc[2 * ks][2] * inv1, sacc[2 * ks][3] * inv1);
        __half2 p2 = __floats2half2_rn(sacc[2 * ks + 1][0] * inv0, sacc[2 * ks + 1][1] * inv0);
        __half2 p3 = __floats2half2_rn(sacc[2 * ks + 1][2] * inv1, sacc[2 * ks + 1][3] * inv1);
        pf[ks][0] = *(uint32_t*)&p0;
        pf[ks][1] = *(uint32_t*)&p1;
        pf[ks][2] = *(uint32_t*)&p2;
        pf[ks][3] = *(uint32_t*)&p3;
    }

    // ---- Phase 2: O = P V, split into two 64-col halves (oacc 32 regs) ----
    const int v_r = (lane & 15);
    const int v_c = (lane >> 4) * 8;
#pragma unroll
    for (int dh = 0; dh < 2; dh++) {
        float oacc[8][4];
#pragma unroll
        for (int i = 0; i < 8; i++)
#pragma unroll
            for (int j = 0; j < 4; j++) oacc[i][j] = 0.0f;

#pragma unroll
        for (int ks = 0; ks < 8; ks++) {
            const int kb = ks * 16;
#pragma unroll
            for (int pl = 0; pl < 4; pl++) {
                const int p = dh * 4 + pl;
                uint32_t bf[4];
                ldsm_x4_t(bf, (uint32_t)__cvta_generic_to_shared(
                              sV + (kb + v_r) * AST + p * 16 + v_c));
                mma_f16(oacc[2 * pl    ], pf[ks], bf);
                mma_f16(oacc[2 * pl + 1], pf[ks], bf + 2);
            }
        }

#pragma unroll
        for (int nt = 0; nt < 8; nt++) {
            int col = cbase + dh * 64 + nt * 8 + 2 * lc;
            size_t g0 = (size_t)(tb + m0 + lr    ) * PD + col;
            size_t g1 = (size_t)(tb + m0 + lr + 8) * PD + col;
            __half2 o0 = __floats2half2_rn(oacc[nt][0], oacc[nt][1]);
            __half2 o1 = __floats2half2_rn(oacc[nt][2], oacc[nt][3]);
            *(uint32_t*)&O[g0] = *(uint32_t*)&o0;
            *(uint32_t*)&O[g1] = *(uint32_t*)&o1;
        }
    }
}

// ---------------------------------------------------------------------------
extern "C" void kernel_launch(void* const* d_in, const int* in_sizes, int n_in,
                              void* d_out, int out_size)
{
    const float* x    = (const float*)d_in[0];
    const float* mask = (const float*)d_in[1];
    const float* wq   = (const float*)d_in[2];
    const float* wk   = (const float*)d_in[3];
    const float* wv   = (const float*)d_in[4];
    const float* wo   = (const float*)d_in[5];
    float* out = (float*)d_out;

    void *pqkv, *pxh, *pwh, *paoh, *pct, *pst;
    cudaGetSymbolAddress(&pqkv, g_qkv);
    cudaGetSymbolAddress(&pxh,  g_xh);
    cudaGetSymbolAddress(&pwh,  g_wh);
    cudaGetSymbolAddress(&paoh, g_aoh);
    cudaGetSymbolAddress(&pct,  g_cos);
    cudaGetSymbolAddress(&pst,  g_sin);
    __half* qkv  = (__half*)pqkv;
    __half* xh   = (__half*)pxh;
    __half* wh   = (__half*)pwh;
    __half* aoh  = (__half*)paoh;
    float*  ctab = (float*)pct;
    float*  stab = (float*)pst;

    // Fused prep (MLP=2) + rope tables
    prep_kernel<<<N4X / 256, 256>>>((const float4*)x,
                                    (const float4*)wq, (const float4*)wk,
                                    (const float4*)wv, (const float4*)wo,
                                    xh, wh);
    rope_table_kernel<<<(PW * 64) / 256, 256>>>(ctab, stab);

    size_t gsmem = (size_t)2 * NST * BM * KST * sizeof(__half);   // 110,592 B
    cudaFuncSetAttribute(gemm_f16<__half>, cudaFuncAttributeMaxDynamicSharedMemorySize,
                         (int)gsmem);
    cudaFuncSetAttribute(gemm_f16<float>, cudaFuncAttributeMaxDynamicSharedMemorySize,
                         (int)gsmem);

    // Fused QKV projection: [8192 x 2048] x [6144 x 2048]^T -> fp16 [8192 x 6144]
    dim3 gqkv(PD3 / BN, PT / BM);            // 48 x 64
    gemm_f16<__half><<<gqkv, 256, gsmem>>>(xh, wh, qkv, PT, PD3, PD);

    // Attention (rope fused; 2 CTAs/SM)
    size_t asmem = (size_t)3 * 128 * AST * sizeof(__half);  // 104,448 B
    cudaFuncSetAttribute(attn_mma, cudaFuncAttributeMaxDynamicSharedMemorySize,
                         (int)asmem);
    attn_mma<<<dim3(PNC, PH, PB), 256, asmem>>>(qkv, mask, ctab, stab, aoh);

    // Output projection (fp32 out)
    dim3 gout(PD / BN, PT / BM);             // 16 x 64
    gemm_f16<float><<<gout, 256, gsmem>>>(aoh, wh + 3 * (size_t)PD * PD, out, PT, PD, PD);
}